// round 9
// baseline (speedup 1.0000x reference)
#include <cuda_runtime.h>
#include <cuda_bf16.h>
#include <cstdint>
#include <math.h>

#define B_    4
#define S_    2048
#define D_    768
#define H_    12
#define HD    64
#define QKV_N (3*D_)      // 2304
#define M_    (B_*S_)     // 8192

// Scratch (no cudaMalloc allowed)
__device__ __nv_bfloat16 g_qh[M_ * QKV_N];   // qkv hi (Q pre-scaled)
__device__ __nv_bfloat16 g_ql[M_ * QKV_N];   // qkv lo
__device__ __nv_bfloat16 g_ah[M_ * D_];
__device__ __nv_bfloat16 g_al[M_ * D_];
__device__ __nv_bfloat16 g_bh[QKV_N * D_];
__device__ __nv_bfloat16 g_bl[QKV_N * D_];

// ---------------------------------------------------------------------------
__device__ __forceinline__ uint32_t smem_u32(const void* p) {
    uint32_t a;
    asm("{ .reg .u64 t; cvta.to.shared.u64 t, %1; cvt.u32.u64 %0, t; }" : "=r"(a) : "l"(p));
    return a;
}

#define CP_ASYNC16(dst, src) \
    asm volatile("cp.async.cg.shared.global [%0], [%1], 16;" :: "r"(dst), "l"(src))
#define CP_COMMIT() asm volatile("cp.async.commit_group;" ::: "memory")
#define CP_WAIT0()  asm volatile("cp.async.wait_group 0;" ::: "memory")

#define LDM_X4(r, addr) \
    asm volatile("ldmatrix.sync.aligned.m8n8.x4.shared.b16 {%0,%1,%2,%3}, [%4];" \
        : "=r"((r)[0]), "=r"((r)[1]), "=r"((r)[2]), "=r"((r)[3]) : "r"(addr))
#define LDM_X4T(r, addr) \
    asm volatile("ldmatrix.sync.aligned.m8n8.x4.trans.shared.b16 {%0,%1,%2,%3}, [%4];" \
        : "=r"((r)[0]), "=r"((r)[1]), "=r"((r)[2]), "=r"((r)[3]) : "r"(addr))
#define LDM_X2(r, addr) \
    asm volatile("ldmatrix.sync.aligned.m8n8.x2.shared.b16 {%0,%1}, [%2];" \
        : "=r"((r)[0]), "=r"((r)[1]) : "r"(addr))
#define MMA_BF16(d, a, b) \
    asm volatile("mma.sync.aligned.m16n8k16.row.col.f32.bf16.bf16.f32 " \
        "{%0,%1,%2,%3}, {%4,%5,%6,%7}, {%8,%9}, {%0,%1,%2,%3};" \
        : "+f"((d)[0]), "+f"((d)[1]), "+f"((d)[2]), "+f"((d)[3]) \
        : "r"((a)[0]), "r"((a)[1]), "r"((a)[2]), "r"((a)[3]), \
          "r"((b)[0]), "r"((b)[1]))
#define MMA_BF16R(d, a, b0r, b1r) \
    asm volatile("mma.sync.aligned.m16n8k16.row.col.f32.bf16.bf16.f32 " \
        "{%0,%1,%2,%3}, {%4,%5,%6,%7}, {%8,%9}, {%0,%1,%2,%3};" \
        : "+f"((d)[0]), "+f"((d)[1]), "+f"((d)[2]), "+f"((d)[3]) \
        : "r"((a)[0]), "r"((a)[1]), "r"((a)[2]), "r"((a)[3]), \
          "r"(b0r), "r"(b1r))

__device__ __forceinline__ uint32_t pack_bf2(float lo, float hi) {
    uint32_t r;
    asm("cvt.rn.bf16x2.f32 %0, %1, %2;" : "=r"(r) : "f"(hi), "f"(lo));
    return r;
}

__device__ __forceinline__ void store_split4(__nv_bfloat16* ph, __nv_bfloat16* pl, float4 v) {
    __nv_bfloat16 h0 = __float2bfloat16(v.x), h1 = __float2bfloat16(v.y);
    __nv_bfloat16 h2 = __float2bfloat16(v.z), h3 = __float2bfloat16(v.w);
    *(__nv_bfloat162*)(ph)     = __nv_bfloat162(h0, h1);
    *(__nv_bfloat162*)(ph + 2) = __nv_bfloat162(h2, h3);
    *(__nv_bfloat162*)(pl)     = __nv_bfloat162(
        __float2bfloat16(v.x - __bfloat162float(h0)),
        __float2bfloat16(v.y - __bfloat162float(h1)));
    *(__nv_bfloat162*)(pl + 2) = __nv_bfloat162(
        __float2bfloat16(v.z - __bfloat162float(h2)),
        __float2bfloat16(v.w - __bfloat162float(h3)));
}

// ---------------------------------------------------------------------------
__global__ void split_kernel(const float* __restrict__ in,
                             __nv_bfloat16* __restrict__ hi,
                             __nv_bfloat16* __restrict__ lo, int n4)
{
    int i = blockIdx.x * blockDim.x + threadIdx.x;
    if (i >= n4) return;
    float4 v = ((const float4*)in)[i];
    store_split4(hi + 4 * (long)i, lo + 4 * (long)i, v);
}

__global__ void transpose_split_kernel(const float* __restrict__ W,
                                       __nv_bfloat16* __restrict__ Bh,
                                       __nv_bfloat16* __restrict__ Bl,
                                       int K, int N)
{
    __shared__ float t[32][33];
    int n0 = blockIdx.x * 32, k0 = blockIdx.y * 32;
    int tx = threadIdx.x, ty = threadIdx.y;
#pragma unroll
    for (int j = 0; j < 4; ++j)
        t[ty + j*8][tx] = W[(long)(k0 + ty + j*8) * N + n0 + tx];
    __syncthreads();
#pragma unroll
    for (int j = 0; j < 4; ++j) {
        float v = t[tx][ty + j*8];
        __nv_bfloat16 h = __float2bfloat16(v);
        __nv_bfloat16 l = __float2bfloat16(v - __bfloat162float(h));
        long o = (long)(n0 + ty + j*8) * K + k0 + tx;
        Bh[o] = h;
        Bl[o] = l;
    }
}

// ---------------------------------------------------------------------------
// bf16x3 GEMM via mma.sync, cp.async double-buffered.
// ---------------------------------------------------------------------------
#define LDA 40
#define G_ARR (128 * LDA * 2)
#define G_STAGE (4 * G_ARR)
#define G_SMEM (2 * G_STAGE)

template<int SPLIT_OUT>
__global__ __launch_bounds__(256)
void gemm_mma_kernel(const __nv_bfloat16* __restrict__ Ah,
                     const __nv_bfloat16* __restrict__ Al,
                     const __nv_bfloat16* __restrict__ Bh,
                     const __nv_bfloat16* __restrict__ Bl,
                     const float* __restrict__ bias,
                     float* __restrict__ C,
                     __nv_bfloat16* __restrict__ Ch,
                     __nv_bfloat16* __restrict__ Cl,
                     int M, int N, int K, int scale_cols, float scale)
{
    extern __shared__ __nv_bfloat16 gsm[];
    const uint32_t sb = smem_u32(gsm);

    const int tid  = threadIdx.x;
    const int lane = tid & 31;
    const int wid  = tid >> 5;
    const int wm   = wid >> 2;
    const int wn   = wid & 3;
    const int m0   = blockIdx.y * 128;
    const int n0   = blockIdx.x * 128;
    const int KT   = K / 32;

    const __nv_bfloat16* srcs[4] = {Ah, Al, Bh, Bl};
    const int row0s[4] = {m0, m0, n0, n0};

    float acc[4][4][4];
#pragma unroll
    for (int i = 0; i < 4; ++i)
#pragma unroll
        for (int j = 0; j < 4; ++j)
#pragma unroll
            for (int r = 0; r < 4; ++r) acc[i][j][r] = 0.f;

    const int a_row = lane & 15;
    const int a_kb  = (lane >> 4) * 8;
    const int b_row = lane & 7;
    const int b_kb  = ((lane >> 3) & 1) * 8;

    auto cp_issue = [&](int kt, int stage) {
        const int k0 = kt * 32;
        const uint32_t sdst = sb + stage * G_STAGE;
#pragma unroll
        for (int t = 0; t < 4; ++t) {
            const __nv_bfloat16* src = srcs[t];
            const int r0 = row0s[t];
#pragma unroll
            for (int it = 0; it < 2; ++it) {
                int chunk = tid + it * 256;
                int r = chunk >> 2, c = chunk & 3;
                uint32_t dst = sdst + t * G_ARR + (r * LDA + c * 8) * 2;
                CP_ASYNC16(dst, (const void*)&src[(long)(r0 + r) * K + k0 + c * 8]);
            }
        }
    };

    cp_issue(0, 0);
    CP_COMMIT();

    for (int kt = 0; kt < KT; ++kt) {
        CP_WAIT0();
        __syncthreads();
        if (kt + 1 < KT) { cp_issue(kt + 1, (kt + 1) & 1); CP_COMMIT(); }

        const uint32_t ub  = sb + (kt & 1) * G_STAGE;
        const uint32_t uAh = ub, uAl = ub + G_ARR, uBh = ub + 2 * G_ARR, uBl = ub + 3 * G_ARR;

#pragma unroll
        for (int ks = 0; ks < 2; ++ks) {
            const int kc = ks * 16;
            uint32_t bh[4][2], bl[4][2];
#pragma unroll
            for (int j = 0; j < 4; ++j) {
                uint32_t off = ((wn * 32 + j * 8 + b_row) * LDA + kc + b_kb) * 2;
                LDM_X2(bh[j], uBh + off);
                LDM_X2(bl[j], uBl + off);
            }
#pragma unroll
            for (int i = 0; i < 4; ++i) {
                uint32_t off = ((wm * 64 + i * 16 + a_row) * LDA + kc + a_kb) * 2;
                uint32_t ah[4], al[4];
                LDM_X4(ah, uAh + off);
                LDM_X4(al, uAl + off);
#pragma unroll
                for (int j = 0; j < 4; ++j) {
                    MMA_BF16(acc[i][j], ah, bh[j]);
                    MMA_BF16(acc[i][j], ah, bl[j]);
                    MMA_BF16(acc[i][j], al, bh[j]);
                }
            }
        }
        __syncthreads();
    }

    const int qr = lane >> 2;
    const int qc = (lane & 3) * 2;
#pragma unroll
    for (int i = 0; i < 4; ++i) {
#pragma unroll
        for (int j = 0; j < 4; ++j) {
            int col = n0 + wn * 32 + j * 8 + qc;
            float b0 = __ldg(&bias[col]);
            float b1 = __ldg(&bias[col + 1]);
            long r0 = m0 + wm * 64 + i * 16 + qr;
            float v00 = acc[i][j][0] + b0, v01 = acc[i][j][1] + b1;
            float v10 = acc[i][j][2] + b0, v11 = acc[i][j][3] + b1;
            if (SPLIT_OUT) {
                float s = (col < scale_cols) ? scale : 1.f;
                v00 *= s; v01 *= s; v10 *= s; v11 *= s;
                __nv_bfloat16 h00 = __float2bfloat16(v00), h01 = __float2bfloat16(v01);
                __nv_bfloat16 h10 = __float2bfloat16(v10), h11 = __float2bfloat16(v11);
                *(__nv_bfloat162*)&Ch[r0 * N + col] = __nv_bfloat162(h00, h01);
                *(__nv_bfloat162*)&Cl[r0 * N + col] = __nv_bfloat162(
                    __float2bfloat16(v00 - __bfloat162float(h00)),
                    __float2bfloat16(v01 - __bfloat162float(h01)));
                *(__nv_bfloat162*)&Ch[(r0 + 8) * N + col] = __nv_bfloat162(h10, h11);
                *(__nv_bfloat162*)&Cl[(r0 + 8) * N + col] = __nv_bfloat162(
                    __float2bfloat16(v10 - __bfloat162float(h10)),
                    __float2bfloat16(v11 - __bfloat162float(h11)));
            } else {
                *(float2*)&C[r0 * N + col]       = make_float2(v00, v01);
                *(float2*)&C[(r0 + 8) * N + col] = make_float2(v10, v11);
            }
        }
    }
}

// ---------------------------------------------------------------------------
// Flash attention, bf16 hi/lo inputs, cp.async double-buffered K/V.
// Loop order chosen so consecutive MMAs hit independent accumulators.
// ---------------------------------------------------------------------------
#define FA_LD 72
#define FA_ARR (128 * FA_LD * 2)
#define FA_KV0 (2 * FA_ARR)
#define FA_STAGE (4 * FA_ARR)
#define FA_SMEM (FA_KV0 + 2 * FA_STAGE)   // 184320

__global__ __launch_bounds__(256)
void flash_mma_kernel(const __nv_bfloat16* __restrict__ qh,
                      const __nv_bfloat16* __restrict__ ql,
                      __nv_bfloat16* __restrict__ oh,
                      __nv_bfloat16* __restrict__ ol)
{
    extern __shared__ __nv_bfloat16 fsm[];
    const uint32_t sb = smem_u32(fsm);

    const int tid  = threadIdx.x;
    const int lane = tid & 31;
    const int wq   = tid >> 5;
    const int qt   = (int)gridDim.x - 1 - (int)blockIdx.x;
    const int bh   = blockIdx.y;
    const int b    = bh / H_;
    const int h    = bh - b * H_;
    const int q0   = qt * 128;
    const long rowbase = (long)b * S_ * QKV_N + h * HD;

    const __nv_bfloat16* kvsrc[4] = {qh + D_, ql + D_, qh + 2 * D_, ql + 2 * D_};

    {
        const __nv_bfloat16* qsrc[2] = {qh, ql};
#pragma unroll
        for (int t = 0; t < 2; ++t) {
#pragma unroll
            for (int it = 0; it < 4; ++it) {
                int chunk = tid + it * 256;
                int r = chunk >> 3, c = chunk & 7;
                uint32_t dst = sb + t * FA_ARR + (r * FA_LD + c * 8) * 2;
                CP_ASYNC16(dst, (const void*)&qsrc[t][rowbase + (long)(q0 + r) * QKV_N + c * 8]);
            }
        }
    }
    auto kv_issue = [&](int kt, int stage) {
        const int k0 = kt * 128;
        const uint32_t sdst = sb + FA_KV0 + stage * FA_STAGE;
#pragma unroll
        for (int t = 0; t < 4; ++t) {
#pragma unroll
            for (int it = 0; it < 4; ++it) {
                int chunk = tid + it * 256;
                int r = chunk >> 3, c = chunk & 7;
                uint32_t dst = sdst + t * FA_ARR + (r * FA_LD + c * 8) * 2;
                CP_ASYNC16(dst, (const void*)&kvsrc[t][rowbase + (long)(k0 + r) * QKV_N + c * 8]);
            }
        }
    };
    kv_issue(0, 0);
    CP_COMMIT();
    CP_WAIT0();
    __syncthreads();

    uint32_t qfh[4][4], qfl[4][4];
    {
        int arow = wq * 16 + (lane & 15);
        int acol = (lane >> 4) * 8;
#pragma unroll
        for (int ks = 0; ks < 4; ++ks) {
            uint32_t off = (arow * FA_LD + ks * 16 + acol) * 2;
            LDM_X4(qfh[ks], sb + off);
            LDM_X4(qfl[ks], sb + FA_ARR + off);
        }
    }

    float o[8][4];
#pragma unroll
    for (int j = 0; j < 8; ++j)
#pragma unroll
        for (int r = 0; r < 4; ++r) o[j][r] = 0.f;
    float rm[2] = {-1e30f, -1e30f};
    float rl[2] = {0.f, 0.f};

    const int r0 = lane >> 2;
    const int c0 = (lane & 3) * 2;
    const int krow = (lane & 15);
    const int kcol = (lane >> 4) * 8;
    const int vr = (lane & 7) + ((lane >> 3) & 1) * 8;
    const int vc = (lane >> 4) * 8;

    for (int kt = 0; kt <= qt; ++kt) {
        if (kt < qt) { kv_issue(kt + 1, (kt + 1) & 1); CP_COMMIT(); }

        const uint32_t ukv = sb + FA_KV0 + (kt & 1) * FA_STAGE;
        const uint32_t uKh = ukv, uKl = ukv + FA_ARR;
        const uint32_t uVh = ukv + 2 * FA_ARR, uVl = ukv + 3 * FA_ARR;

        // S = Q K^T  -- ks OUTER so consecutive j2 hit independent accumulators
        float sc[16][4];
#pragma unroll
        for (int j = 0; j < 16; ++j)
#pragma unroll
            for (int r = 0; r < 4; ++r) sc[j][r] = 0.f;

#pragma unroll
        for (int ks = 0; ks < 4; ++ks) {
#pragma unroll
            for (int j2 = 0; j2 < 8; ++j2) {
                uint32_t off = ((j2 * 16 + krow) * FA_LD + ks * 16 + kcol) * 2;
                uint32_t kh[4], kl[4];
                LDM_X4(kh, uKh + off);
                LDM_X4(kl, uKl + off);
                // interleave the two accumulators to break RAW back-to-backs
                MMA_BF16R(sc[2*j2],   qfh[ks], kh[0], kh[2]);
                MMA_BF16R(sc[2*j2+1], qfh[ks], kh[1], kh[3]);
                MMA_BF16R(sc[2*j2],   qfh[ks], kl[0], kl[2]);
                MMA_BF16R(sc[2*j2+1], qfh[ks], kl[1], kl[3]);
                MMA_BF16R(sc[2*j2],   qfl[ks], kh[0], kh[2]);
                MMA_BF16R(sc[2*j2+1], qfl[ks], kh[1], kh[3]);
            }
        }

        if (kt == qt) {
            int row0 = wq * 16 + r0;
            int row1 = row0 + 8;
#pragma unroll
            for (int j = 0; j < 16; ++j) {
                int col = j * 8 + c0;
                if (col     > row0) sc[j][0] = -1e30f;
                if (col + 1 > row0) sc[j][1] = -1e30f;
                if (col     > row1) sc[j][2] = -1e30f;
                if (col + 1 > row1) sc[j][3] = -1e30f;
            }
        }

        // online softmax
        float mx0 = -1e30f, mx1 = -1e30f;
#pragma unroll
        for (int j = 0; j < 16; ++j) {
            mx0 = fmaxf(mx0, fmaxf(sc[j][0], sc[j][1]));
            mx1 = fmaxf(mx1, fmaxf(sc[j][2], sc[j][3]));
        }
        mx0 = fmaxf(mx0, __shfl_xor_sync(0xffffffffu, mx0, 1));
        mx0 = fmaxf(mx0, __shfl_xor_sync(0xffffffffu, mx0, 2));
        mx1 = fmaxf(mx1, __shfl_xor_sync(0xffffffffu, mx1, 1));
        mx1 = fmaxf(mx1, __shfl_xor_sync(0xffffffffu, mx1, 2));

        float mn0 = fmaxf(rm[0], mx0);
        float mn1 = fmaxf(rm[1], mx1);
        float a0 = __expf(rm[0] - mn0);
        float a1 = __expf(rm[1] - mn1);
        rm[0] = mn0; rm[1] = mn1;

        float s0 = 0.f, s1 = 0.f;
#pragma unroll
        for (int j = 0; j < 16; ++j) {
            sc[j][0] = __expf(sc[j][0] - mn0); s0 += sc[j][0];
            sc[j][1] = __expf(sc[j][1] - mn0); s0 += sc[j][1];
            sc[j][2] = __expf(sc[j][2] - mn1); s1 += sc[j][2];
            sc[j][3] = __expf(sc[j][3] - mn1); s1 += sc[j][3];
        }
        s0 += __shfl_xor_sync(0xffffffffu, s0, 1);
        s0 += __shfl_xor_sync(0xffffffffu, s0, 2);
        s1 += __shfl_xor_sync(0xffffffffu, s1, 1);
        s1 += __shfl_xor_sync(0xffffffffu, s1, 2);
        rl[0] = rl[0] * a0 + s0;
        rl[1] = rl[1] * a1 + s1;
#pragma unroll
        for (int j = 0; j < 8; ++j) {
            o[j][0] *= a0; o[j][1] *= a0;
            o[j][2] *= a1; o[j][3] *= a1;
        }

        // O += P V  -- jp inner (independent accumulators), interleaved pairs
#pragma unroll
        for (int ks2 = 0; ks2 < 8; ++ks2) {
            uint32_t pfh[4], pfl[4];
#pragma unroll
            for (int half = 0; half < 2; ++half) {
                const float* p = sc[2*ks2 + half];
                float h0f = __bfloat162float(__float2bfloat16(p[0]));
                float h1f = __bfloat162float(__float2bfloat16(p[1]));
                float h2f = __bfloat162float(__float2bfloat16(p[2]));
                float h3f = __bfloat162float(__float2bfloat16(p[3]));
                pfh[2*half]   = pack_bf2(h0f, h1f);
                pfh[2*half+1] = pack_bf2(h2f, h3f);
                pfl[2*half]   = pack_bf2(p[0]-h0f, p[1]-h1f);
                pfl[2*half+1] = pack_bf2(p[2]-h2f, p[3]-h3f);
            }
#pragma unroll
            for (int jp = 0; jp < 4; ++jp) {
                uint32_t voff = ((ks2 * 16 + vr) * FA_LD + jp * 16 + vc) * 2;
                uint32_t vh[4], vl[4];
                LDM_X4T(vh, uVh + voff);
                LDM_X4T(vl, uVl + voff);
                MMA_BF16R(o[2*jp],   pfh, vh[0], vh[1]);
                MMA_BF16R(o[2*jp+1], pfh, vh[2], vh[3]);
                MMA_BF16R(o[2*jp],   pfh, vl[0], vl[1]);
                MMA_BF16R(o[2*jp+1], pfh, vl[2], vl[3]);
                MMA_BF16R(o[2*jp],   pfl, vh[0], vh[1]);
                MMA_BF16R(o[2*jp+1], pfl, vh[2], vh[3]);
            }
        }

        if (kt < qt) { CP_WAIT0(); __syncthreads(); }
    }

    // epilogue
    float inv0 = 1.f / rl[0];
    float inv1 = 1.f / rl[1];
    long grow0 = (long)b * S_ + q0 + wq * 16 + r0;
#pragma unroll
    for (int j = 0; j < 8; ++j) {
        int col = h * HD + j * 8 + c0;
        {
            float v0 = o[j][0] * inv0, v1 = o[j][1] * inv0;
            __nv_bfloat16 h0 = __float2bfloat16(v0), h1 = __float2bfloat16(v1);
            long off = grow0 * D_ + col;
            *(__nv_bfloat162*)&oh[off] = __nv_bfloat162(h0, h1);
            *(__nv_bfloat162*)&ol[off] = __nv_bfloat162(
                __float2bfloat16(v0 - __bfloat162float(h0)),
                __float2bfloat16(v1 - __bfloat162float(h1)));
        }
        {
            float v0 = o[j][2] * inv1, v1 = o[j][3] * inv1;
            __nv_bfloat16 h0 = __float2bfloat16(v0), h1 = __float2bfloat16(v1);
            long off = (grow0 + 8) * D_ + col;
            *(__nv_bfloat162*)&oh[off] = __nv_bfloat162(h0, h1);
            *(__nv_bfloat162*)&ol[off] = __nv_bfloat162(
                __float2bfloat16(v0 - __bfloat162float(h0)),
                __float2bfloat16(v1 - __bfloat162float(h1)));
        }
    }
}

// ---------------------------------------------------------------------------
extern "C" void kernel_launch(void* const* d_in, const int* in_sizes, int n_in,
                              void* d_out, int out_size)
{
    const float* x    = (const float*)d_in[0];
    const float* Wqkv = (const float*)d_in[1];
    const float* bqkv = (const float*)d_in[2];
    const float* Wp   = (const float*)d_in[3];
    const float* bp   = (const float*)d_in[4];
    float* out = (float*)d_out;

    __nv_bfloat16 *qh, *ql, *ah, *al, *bh, *bl;
    cudaGetSymbolAddress((void**)&qh, g_qh);
    cudaGetSymbolAddress((void**)&ql, g_ql);
    cudaGetSymbolAddress((void**)&ah, g_ah);
    cudaGetSymbolAddress((void**)&al, g_al);
    cudaGetSymbolAddress((void**)&bh, g_bh);
    cudaGetSymbolAddress((void**)&bl, g_bl);

    cudaFuncSetAttribute(gemm_mma_kernel<1>,
                         cudaFuncAttributeMaxDynamicSharedMemorySize, G_SMEM);
    cudaFuncSetAttribute(gemm_mma_kernel<0>,
                         cudaFuncAttributeMaxDynamicSharedMemorySize, G_SMEM);
    cudaFuncSetAttribute(flash_mma_kernel,
                         cudaFuncAttributeMaxDynamicSharedMemorySize, FA_SMEM);

    const int n4 = M_ * D_ / 4;

    split_kernel<<<(n4 + 255) / 256, 256>>>(x, ah, al, n4);
    transpose_split_kernel<<<dim3(QKV_N / 32, D_ / 32), dim3(32, 8)>>>(Wqkv, bh, bl, D_, QKV_N);
    gemm_mma_kernel<1><<<dim3(QKV_N / 128, M_ / 128), 256, G_SMEM>>>(
        ah, al, bh, bl, bqkv, nullptr, qh, ql, M_, QKV_N, D_, D_, 0.125f);

    flash_mma_kernel<<<dim3(S_ / 128, B_ * H_), 256, FA_SMEM>>>(qh, ql, ah, al);

    transpose_split_kernel<<<dim3(D_ / 32, D_ / 32), dim3(32, 8)>>>(Wp, bh, bl, D_, D_);
    gemm_mma_kernel<0><<<dim3(D_ / 128, M_ / 128), 256, G_SMEM>>>(
        ah, al, bh, bl, bp, out, nullptr, nullptr, M_, D_, D_, 0, 1.f);
}

// round 10
// speedup vs baseline: 1.0001x; 1.0001x over previous
#include <cuda_runtime.h>
#include <cuda_bf16.h>
#include <cstdint>
#include <math.h>

#define B_    4
#define S_    2048
#define D_    768
#define H_    12
#define HD    64
#define QKV_N (3*D_)      // 2304
#define M_    (B_*S_)     // 8192

// Scratch (no cudaMalloc allowed)
__device__ __nv_bfloat16 g_qh[M_ * QKV_N];   // qkv hi (Q pre-scaled by 0.125*log2e)
__device__ __nv_bfloat16 g_ql[M_ * QKV_N];   // qkv lo
__device__ __nv_bfloat16 g_ah[M_ * D_];
__device__ __nv_bfloat16 g_al[M_ * D_];
__device__ __nv_bfloat16 g_bh[QKV_N * D_];
__device__ __nv_bfloat16 g_bl[QKV_N * D_];

// ---------------------------------------------------------------------------
__device__ __forceinline__ uint32_t smem_u32(const void* p) {
    uint32_t a;
    asm("{ .reg .u64 t; cvta.to.shared.u64 t, %1; cvt.u32.u64 %0, t; }" : "=r"(a) : "l"(p));
    return a;
}

#define CP_ASYNC16(dst, src) \
    asm volatile("cp.async.cg.shared.global [%0], [%1], 16;" :: "r"(dst), "l"(src))
#define CP_COMMIT() asm volatile("cp.async.commit_group;" ::: "memory")
#define CP_WAIT0()  asm volatile("cp.async.wait_group 0;" ::: "memory")

#define LDM_X4(r, addr) \
    asm volatile("ldmatrix.sync.aligned.m8n8.x4.shared.b16 {%0,%1,%2,%3}, [%4];" \
        : "=r"((r)[0]), "=r"((r)[1]), "=r"((r)[2]), "=r"((r)[3]) : "r"(addr))
#define LDM_X4T(r, addr) \
    asm volatile("ldmatrix.sync.aligned.m8n8.x4.trans.shared.b16 {%0,%1,%2,%3}, [%4];" \
        : "=r"((r)[0]), "=r"((r)[1]), "=r"((r)[2]), "=r"((r)[3]) : "r"(addr))
#define LDM_X2(r, addr) \
    asm volatile("ldmatrix.sync.aligned.m8n8.x2.shared.b16 {%0,%1}, [%2];" \
        : "=r"((r)[0]), "=r"((r)[1]) : "r"(addr))
#define MMA_BF16(d, a, b) \
    asm volatile("mma.sync.aligned.m16n8k16.row.col.f32.bf16.bf16.f32 " \
        "{%0,%1,%2,%3}, {%4,%5,%6,%7}, {%8,%9}, {%0,%1,%2,%3};" \
        : "+f"((d)[0]), "+f"((d)[1]), "+f"((d)[2]), "+f"((d)[3]) \
        : "r"((a)[0]), "r"((a)[1]), "r"((a)[2]), "r"((a)[3]), \
          "r"((b)[0]), "r"((b)[1]))
#define MMA_BF16R(d, a, b0r, b1r) \
    asm volatile("mma.sync.aligned.m16n8k16.row.col.f32.bf16.bf16.f32 " \
        "{%0,%1,%2,%3}, {%4,%5,%6,%7}, {%8,%9}, {%0,%1,%2,%3};" \
        : "+f"((d)[0]), "+f"((d)[1]), "+f"((d)[2]), "+f"((d)[3]) \
        : "r"((a)[0]), "r"((a)[1]), "r"((a)[2]), "r"((a)[3]), \
          "r"(b0r), "r"(b1r))

__device__ __forceinline__ uint32_t pack_bf2(float lo, float hi) {
    uint32_t r;
    asm("cvt.rn.bf16x2.f32 %0, %1, %2;" : "=r"(r) : "f"(hi), "f"(lo));
    return r;
}

__device__ __forceinline__ void store_split4(__nv_bfloat16* ph, __nv_bfloat16* pl, float4 v) {
    __nv_bfloat16 h0 = __float2bfloat16(v.x), h1 = __float2bfloat16(v.y);
    __nv_bfloat16 h2 = __float2bfloat16(v.z), h3 = __float2bfloat16(v.w);
    *(__nv_bfloat162*)(ph)     = __nv_bfloat162(h0, h1);
    *(__nv_bfloat162*)(ph + 2) = __nv_bfloat162(h2, h3);
    *(__nv_bfloat162*)(pl)     = __nv_bfloat162(
        __float2bfloat16(v.x - __bfloat162float(h0)),
        __float2bfloat16(v.y - __bfloat162float(h1)));
    *(__nv_bfloat162*)(pl + 2) = __nv_bfloat162(
        __float2bfloat16(v.z - __bfloat162float(h2)),
        __float2bfloat16(v.w - __bfloat162float(h3)));
}

// ---------------------------------------------------------------------------
__global__ void split_kernel(const float* __restrict__ in,
                             __nv_bfloat16* __restrict__ hi,
                             __nv_bfloat16* __restrict__ lo, int n4)
{
    int i = blockIdx.x * blockDim.x + threadIdx.x;
    if (i >= n4) return;
    float4 v = ((const float4*)in)[i];
    store_split4(hi + 4 * (long)i, lo + 4 * (long)i, v);
}

__global__ void transpose_split_kernel(const float* __restrict__ W,
                                       __nv_bfloat16* __restrict__ Bh,
                                       __nv_bfloat16* __restrict__ Bl,
                                       int K, int N)
{
    __shared__ float t[32][33];
    int n0 = blockIdx.x * 32, k0 = blockIdx.y * 32;
    int tx = threadIdx.x, ty = threadIdx.y;
#pragma unroll
    for (int j = 0; j < 4; ++j)
        t[ty + j*8][tx] = W[(long)(k0 + ty + j*8) * N + n0 + tx];
    __syncthreads();
#pragma unroll
    for (int j = 0; j < 4; ++j) {
        float v = t[tx][ty + j*8];
        __nv_bfloat16 h = __float2bfloat16(v);
        __nv_bfloat16 l = __float2bfloat16(v - __bfloat162float(h));
        long o = (long)(n0 + ty + j*8) * K + k0 + tx;
        Bh[o] = h;
        Bl[o] = l;
    }
}

// ---------------------------------------------------------------------------
// bf16x3 GEMM via mma.sync, cp.async double-buffered.
// ---------------------------------------------------------------------------
#define LDA 40
#define G_ARR (128 * LDA * 2)
#define G_STAGE (4 * G_ARR)
#define G_SMEM (2 * G_STAGE)

template<int SPLIT_OUT>
__global__ __launch_bounds__(256)
void gemm_mma_kernel(const __nv_bfloat16* __restrict__ Ah,
                     const __nv_bfloat16* __restrict__ Al,
                     const __nv_bfloat16* __restrict__ Bh,
                     const __nv_bfloat16* __restrict__ Bl,
                     const float* __restrict__ bias,
                     float* __restrict__ C,
                     __nv_bfloat16* __restrict__ Ch,
                     __nv_bfloat16* __restrict__ Cl,
                     int M, int N, int K, int scale_cols, float scale)
{
    extern __shared__ __nv_bfloat16 gsm[];
    const uint32_t sb = smem_u32(gsm);

    const int tid  = threadIdx.x;
    const int lane = tid & 31;
    const int wid  = tid >> 5;
    const int wm   = wid >> 2;
    const int wn   = wid & 3;
    const int m0   = blockIdx.y * 128;
    const int n0   = blockIdx.x * 128;
    const int KT   = K / 32;

    const __nv_bfloat16* srcs[4] = {Ah, Al, Bh, Bl};
    const int row0s[4] = {m0, m0, n0, n0};

    float acc[4][4][4];
#pragma unroll
    for (int i = 0; i < 4; ++i)
#pragma unroll
        for (int j = 0; j < 4; ++j)
#pragma unroll
            for (int r = 0; r < 4; ++r) acc[i][j][r] = 0.f;

    const int a_row = lane & 15;
    const int a_kb  = (lane >> 4) * 8;
    const int b_row = lane & 7;
    const int b_kb  = ((lane >> 3) & 1) * 8;

    auto cp_issue = [&](int kt, int stage) {
        const int k0 = kt * 32;
        const uint32_t sdst = sb + stage * G_STAGE;
#pragma unroll
        for (int t = 0; t < 4; ++t) {
            const __nv_bfloat16* src = srcs[t];
            const int r0 = row0s[t];
#pragma unroll
            for (int it = 0; it < 2; ++it) {
                int chunk = tid + it * 256;
                int r = chunk >> 2, c = chunk & 3;
                uint32_t dst = sdst + t * G_ARR + (r * LDA + c * 8) * 2;
                CP_ASYNC16(dst, (const void*)&src[(long)(r0 + r) * K + k0 + c * 8]);
            }
        }
    };

    cp_issue(0, 0);
    CP_COMMIT();

    for (int kt = 0; kt < KT; ++kt) {
        CP_WAIT0();
        __syncthreads();
        if (kt + 1 < KT) { cp_issue(kt + 1, (kt + 1) & 1); CP_COMMIT(); }

        const uint32_t ub  = sb + (kt & 1) * G_STAGE;
        const uint32_t uAh = ub, uAl = ub + G_ARR, uBh = ub + 2 * G_ARR, uBl = ub + 3 * G_ARR;

#pragma unroll
        for (int ks = 0; ks < 2; ++ks) {
            const int kc = ks * 16;
            uint32_t bh[4][2], bl[4][2];
#pragma unroll
            for (int j = 0; j < 4; ++j) {
                uint32_t off = ((wn * 32 + j * 8 + b_row) * LDA + kc + b_kb) * 2;
                LDM_X2(bh[j], uBh + off);
                LDM_X2(bl[j], uBl + off);
            }
#pragma unroll
            for (int i = 0; i < 4; ++i) {
                uint32_t off = ((wm * 64 + i * 16 + a_row) * LDA + kc + a_kb) * 2;
                uint32_t ah[4], al[4];
                LDM_X4(ah, uAh + off);
                LDM_X4(al, uAl + off);
#pragma unroll
                for (int j = 0; j < 4; ++j) {
                    MMA_BF16(acc[i][j], ah, bh[j]);
                    MMA_BF16(acc[i][j], ah, bl[j]);
                    MMA_BF16(acc[i][j], al, bh[j]);
                }
            }
        }
        __syncthreads();
    }

    const int qr = lane >> 2;
    const int qc = (lane & 3) * 2;
#pragma unroll
    for (int i = 0; i < 4; ++i) {
#pragma unroll
        for (int j = 0; j < 4; ++j) {
            int col = n0 + wn * 32 + j * 8 + qc;
            float b0 = __ldg(&bias[col]);
            float b1 = __ldg(&bias[col + 1]);
            long r0 = m0 + wm * 64 + i * 16 + qr;
            float v00 = acc[i][j][0] + b0, v01 = acc[i][j][1] + b1;
            float v10 = acc[i][j][2] + b0, v11 = acc[i][j][3] + b1;
            if (SPLIT_OUT) {
                float s = (col < scale_cols) ? scale : 1.f;
                v00 *= s; v01 *= s; v10 *= s; v11 *= s;
                __nv_bfloat16 h00 = __float2bfloat16(v00), h01 = __float2bfloat16(v01);
                __nv_bfloat16 h10 = __float2bfloat16(v10), h11 = __float2bfloat16(v11);
                *(__nv_bfloat162*)&Ch[r0 * N + col] = __nv_bfloat162(h00, h01);
                *(__nv_bfloat162*)&Cl[r0 * N + col] = __nv_bfloat162(
                    __float2bfloat16(v00 - __bfloat162float(h00)),
                    __float2bfloat16(v01 - __bfloat162float(h01)));
                *(__nv_bfloat162*)&Ch[(r0 + 8) * N + col] = __nv_bfloat162(h10, h11);
                *(__nv_bfloat162*)&Cl[(r0 + 8) * N + col] = __nv_bfloat162(
                    __float2bfloat16(v10 - __bfloat162float(h10)),
                    __float2bfloat16(v11 - __bfloat162float(h11)));
            } else {
                *(float2*)&C[r0 * N + col]       = make_float2(v00, v01);
                *(float2*)&C[(r0 + 8) * N + col] = make_float2(v10, v11);
            }
        }
    }
}

// ---------------------------------------------------------------------------
// Flash attention, 2 CTAs/SM: 64-key half-tiles (sc[8][4]), Q reloaded from
// smem (no hoisted fragments), exp2-domain softmax. cp.async double-buffered.
// ---------------------------------------------------------------------------
#define FA_LD 72
#define FA_QARR (128 * FA_LD * 2)     // 18432
#define FA_HARR (64 * FA_LD * 2)      // 9216
#define FA_KV0 (2 * FA_QARR)          // 36864
#define FA_STAGE (4 * FA_HARR)        // 36864
#define FA_SMEM (FA_KV0 + 2 * FA_STAGE)  // 110592  (x2 CTAs = 221KB <= 228KB)

__global__ __launch_bounds__(256, 2)
void flash_mma_kernel(const __nv_bfloat16* __restrict__ qh,
                      const __nv_bfloat16* __restrict__ ql,
                      __nv_bfloat16* __restrict__ oh,
                      __nv_bfloat16* __restrict__ ol)
{
    extern __shared__ __nv_bfloat16 fsm[];
    const uint32_t sb = smem_u32(fsm);

    const int tid  = threadIdx.x;
    const int lane = tid & 31;
    const int wq   = tid >> 5;
    const int qt   = (int)gridDim.x - 1 - (int)blockIdx.x;   // big tiles first
    const int bh   = blockIdx.y;
    const int b    = bh / H_;
    const int h    = bh - b * H_;
    const int q0   = qt * 128;
    const long rowbase = (long)b * S_ * QKV_N + h * HD;

    const __nv_bfloat16* kvsrc[4] = {qh + D_, ql + D_, qh + 2 * D_, ql + 2 * D_};

    // prologue: Q (hi/lo, 128 rows)
    {
        const __nv_bfloat16* qsrc[2] = {qh, ql};
#pragma unroll
        for (int t = 0; t < 2; ++t) {
#pragma unroll
            for (int it = 0; it < 4; ++it) {
                int chunk = tid + it * 256;
                int r = chunk >> 3, c = chunk & 7;
                uint32_t dst = sb + t * FA_QARR + (r * FA_LD + c * 8) * 2;
                CP_ASYNC16(dst, (const void*)&qsrc[t][rowbase + (long)(q0 + r) * QKV_N + c * 8]);
            }
        }
    }
    // KV half-tile issue: ht = global 64-key half index
    auto kv_issue = [&](int ht, int stage) {
        const int k0 = ht * 64;
        const uint32_t sdst = sb + FA_KV0 + stage * FA_STAGE;
#pragma unroll
        for (int t = 0; t < 4; ++t) {
#pragma unroll
            for (int it = 0; it < 2; ++it) {
                int chunk = tid + it * 256;
                int r = chunk >> 3, c = chunk & 7;
                uint32_t dst = sdst + t * FA_HARR + (r * FA_LD + c * 8) * 2;
                CP_ASYNC16(dst, (const void*)&kvsrc[t][rowbase + (long)(k0 + r) * QKV_N + c * 8]);
            }
        }
    };
    kv_issue(0, 0);
    CP_COMMIT();
    CP_WAIT0();
    __syncthreads();

    float o[8][4];
#pragma unroll
    for (int j = 0; j < 8; ++j)
#pragma unroll
        for (int r = 0; r < 4; ++r) o[j][r] = 0.f;
    float rm[2] = {-1e30f, -1e30f};
    float rl[2] = {0.f, 0.f};

    const int r0 = lane >> 2;
    const int c0 = (lane & 3) * 2;
    const int arow = wq * 16 + (lane & 15);
    const int acol = (lane >> 4) * 8;
    const int krow = (lane & 15);
    const int kcol = (lane >> 4) * 8;
    const int vr = (lane & 7) + ((lane >> 3) & 1) * 8;
    const int vc = (lane >> 4) * 8;

    const int nh = 2 * (qt + 1);
    for (int ht = 0; ht < nh; ++ht) {
        if (ht + 1 < nh) { kv_issue(ht + 1, (ht + 1) & 1); CP_COMMIT(); }

        const uint32_t ukv = sb + FA_KV0 + (ht & 1) * FA_STAGE;
        const uint32_t uKh = ukv, uKl = ukv + FA_HARR;
        const uint32_t uVh = ukv + 2 * FA_HARR, uVl = ukv + 3 * FA_HARR;

        // S = Q K^T over 64 keys (8 n-tiles of 8)
        float sc[8][4];
#pragma unroll
        for (int j = 0; j < 8; ++j)
#pragma unroll
            for (int r = 0; r < 4; ++r) sc[j][r] = 0.f;

#pragma unroll
        for (int ks = 0; ks < 4; ++ks) {
            uint32_t qfh[4], qfl[4];
            uint32_t qoff = (arow * FA_LD + ks * 16 + acol) * 2;
            LDM_X4(qfh, sb + qoff);
            LDM_X4(qfl, sb + FA_QARR + qoff);
#pragma unroll
            for (int j2 = 0; j2 < 4; ++j2) {
                uint32_t off = ((j2 * 16 + krow) * FA_LD + ks * 16 + kcol) * 2;
                uint32_t kh[4], kl[4];
                LDM_X4(kh, uKh + off);
                LDM_X4(kl, uKl + off);
                MMA_BF16R(sc[2*j2],   qfh, kh[0], kh[2]);
                MMA_BF16R(sc[2*j2+1], qfh, kh[1], kh[3]);
                MMA_BF16R(sc[2*j2],   qfh, kl[0], kl[2]);
                MMA_BF16R(sc[2*j2+1], qfh, kl[1], kl[3]);
                MMA_BF16R(sc[2*j2],   qfl, kh[0], kh[2]);
                MMA_BF16R(sc[2*j2+1], qfl, kh[1], kh[3]);
            }
        }

        // causal mask (diagonal q-tile only)
        if ((ht >> 1) == qt) {
            int cbase = (ht & 1) * 64;
            int row0 = wq * 16 + r0;
            int row1 = row0 + 8;
#pragma unroll
            for (int j = 0; j < 8; ++j) {
                int col = cbase + j * 8 + c0;
                if (col     > row0) sc[j][0] = -1e30f;
                if (col + 1 > row0) sc[j][1] = -1e30f;
                if (col     > row1) sc[j][2] = -1e30f;
                if (col + 1 > row1) sc[j][3] = -1e30f;
            }
        }

        // online softmax (log2 domain; scores pre-scaled by log2e)
        float mx0 = -1e30f, mx1 = -1e30f;
#pragma unroll
        for (int j = 0; j < 8; ++j) {
            mx0 = fmaxf(mx0, fmaxf(sc[j][0], sc[j][1]));
            mx1 = fmaxf(mx1, fmaxf(sc[j][2], sc[j][3]));
        }
        mx0 = fmaxf(mx0, __shfl_xor_sync(0xffffffffu, mx0, 1));
        mx0 = fmaxf(mx0, __shfl_xor_sync(0xffffffffu, mx0, 2));
        mx1 = fmaxf(mx1, __shfl_xor_sync(0xffffffffu, mx1, 1));
        mx1 = fmaxf(mx1, __shfl_xor_sync(0xffffffffu, mx1, 2));

        float mn0 = fmaxf(rm[0], mx0);
        float mn1 = fmaxf(rm[1], mx1);
        float a0 = exp2f(rm[0] - mn0);
        float a1 = exp2f(rm[1] - mn1);
        rm[0] = mn0; rm[1] = mn1;

        float s0 = 0.f, s1 = 0.f;
#pragma unroll
        for (int j = 0; j < 8; ++j) {
            sc[j][0] = exp2f(sc[j][0] - mn0); s0 += sc[j][0];
            sc[j][1] = exp2f(sc[j][1] - mn0); s0 += sc[j][1];
            sc[j][2] = exp2f(sc[j][2] - mn1); s1 += sc[j][2];
            sc[j][3] = exp2f(sc[j][3] - mn1); s1 += sc[j][3];
        }
        s0 += __shfl_xor_sync(0xffffffffu, s0, 1);
        s0 += __shfl_xor_sync(0xffffffffu, s0, 2);
        s1 += __shfl_xor_sync(0xffffffffu, s1, 1);
        s1 += __shfl_xor_sync(0xffffffffu, s1, 2);
        rl[0] = rl[0] * a0 + s0;
        rl[1] = rl[1] * a1 + s1;
#pragma unroll
        for (int j = 0; j < 8; ++j) {
            o[j][0] *= a0; o[j][1] *= a0;
            o[j][2] *= a1; o[j][3] *= a1;
        }

        // O += P V over 64 keys
#pragma unroll
        for (int ks2 = 0; ks2 < 4; ++ks2) {
            uint32_t pfh[4], pfl[4];
#pragma unroll
            for (int half = 0; half < 2; ++half) {
                const float* p = sc[2*ks2 + half];
                float h0f = __bfloat162float(__float2bfloat16(p[0]));
                float h1f = __bfloat162float(__float2bfloat16(p[1]));
                float h2f = __bfloat162float(__float2bfloat16(p[2]));
                float h3f = __bfloat162float(__float2bfloat16(p[3]));
                pfh[2*half]   = pack_bf2(h0f, h1f);
                pfh[2*half+1] = pack_bf2(h2f, h3f);
                pfl[2*half]   = pack_bf2(p[0]-h0f, p[1]-h1f);
                pfl[2*half+1] = pack_bf2(p[2]-h2f, p[3]-h3f);
            }
#pragma unroll
            for (int jp = 0; jp < 4; ++jp) {
                uint32_t voff = ((ks2 * 16 + vr) * FA_LD + jp * 16 + vc) * 2;
                uint32_t vh[4], vl[4];
                LDM_X4T(vh, uVh + voff);
                LDM_X4T(vl, uVl + voff);
                MMA_BF16R(o[2*jp],   pfh, vh[0], vh[1]);
                MMA_BF16R(o[2*jp+1], pfh, vh[2], vh[3]);
                MMA_BF16R(o[2*jp],   pfh, vl[0], vl[1]);
                MMA_BF16R(o[2*jp+1], pfh, vl[2], vl[3]);
                MMA_BF16R(o[2*jp],   pfl, vh[0], vh[1]);
                MMA_BF16R(o[2*jp+1], pfl, vh[2], vh[3]);
            }
        }

        if (ht + 1 < nh) { CP_WAIT0(); __syncthreads(); }
    }

    // epilogue: normalize, split to bf16 hi/lo, store
    float inv0 = 1.f / rl[0];
    float inv1 = 1.f / rl[1];
    long grow0 = (long)b * S_ + q0 + wq * 16 + r0;
#pragma unroll
    for (int j = 0; j < 8; ++j) {
        int col = h * HD + j * 8 + c0;
        {
            float v0 = o[j][0] * inv0, v1 = o[j][1] * inv0;
            __nv_bfloat16 h0 = __float2bfloat16(v0), h1 = __float2bfloat16(v1);
            long off = grow0 * D_ + col;
            *(__nv_bfloat162*)&oh[off] = __nv_bfloat162(h0, h1);
            *(__nv_bfloat162*)&ol[off] = __nv_bfloat162(
                __float2bfloat16(v0 - __bfloat162float(h0)),
                __float2bfloat16(v1 - __bfloat162float(h1)));
        }
        {
            float v0 = o[j][2] * inv1, v1 = o[j][3] * inv1;
            __nv_bfloat16 h0 = __float2bfloat16(v0), h1 = __float2bfloat16(v1);
            long off = (grow0 + 8) * D_ + col;
            *(__nv_bfloat162*)&oh[off] = __nv_bfloat162(h0, h1);
            *(__nv_bfloat162*)&ol[off] = __nv_bfloat162(
                __float2bfloat16(v0 - __bfloat162float(h0)),
                __float2bfloat16(v1 - __bfloat162float(h1)));
        }
    }
}

// ---------------------------------------------------------------------------
extern "C" void kernel_launch(void* const* d_in, const int* in_sizes, int n_in,
                              void* d_out, int out_size)
{
    const float* x    = (const float*)d_in[0];
    const float* Wqkv = (const float*)d_in[1];
    const float* bqkv = (const float*)d_in[2];
    const float* Wp   = (const float*)d_in[3];
    const float* bp   = (const float*)d_in[4];
    float* out = (float*)d_out;

    __nv_bfloat16 *qh, *ql, *ah, *al, *bh, *bl;
    cudaGetSymbolAddress((void**)&qh, g_qh);
    cudaGetSymbolAddress((void**)&ql, g_ql);
    cudaGetSymbolAddress((void**)&ah, g_ah);
    cudaGetSymbolAddress((void**)&al, g_al);
    cudaGetSymbolAddress((void**)&bh, g_bh);
    cudaGetSymbolAddress((void**)&bl, g_bl);

    cudaFuncSetAttribute(gemm_mma_kernel<1>,
                         cudaFuncAttributeMaxDynamicSharedMemorySize, G_SMEM);
    cudaFuncSetAttribute(gemm_mma_kernel<0>,
                         cudaFuncAttributeMaxDynamicSharedMemorySize, G_SMEM);
    cudaFuncSetAttribute(flash_mma_kernel,
                         cudaFuncAttributeMaxDynamicSharedMemorySize, FA_SMEM);

    const int n4 = M_ * D_ / 4;
    const float qscale = 0.125f * 1.44269504088896340736f;   // 1/sqrt(hd) * log2(e)

    split_kernel<<<(n4 + 255) / 256, 256>>>(x, ah, al, n4);
    transpose_split_kernel<<<dim3(QKV_N / 32, D_ / 32), dim3(32, 8)>>>(Wqkv, bh, bl, D_, QKV_N);
    gemm_mma_kernel<1><<<dim3(QKV_N / 128, M_ / 128), 256, G_SMEM>>>(
        ah, al, bh, bl, bqkv, nullptr, qh, ql, M_, QKV_N, D_, D_, qscale);

    flash_mma_kernel<<<dim3(S_ / 128, B_ * H_), 256, FA_SMEM>>>(qh, ql, ah, al);

    transpose_split_kernel<<<dim3(D_ / 32, D_ / 32), dim3(32, 8)>>>(Wp, bh, bl, D_, D_);
    gemm_mma_kernel<0><<<dim3(D_ / 128, M_ / 128), 256, G_SMEM>>>(
        ah, al, bh, bl, bp, out, nullptr, nullptr, M_, D_, D_, 0, 1.f);
}

// round 11
// speedup vs baseline: 1.3995x; 1.3993x over previous
#include <cuda_runtime.h>
#include <cuda_fp16.h>
#include <cstdint>
#include <math.h>

#define B_    4
#define S_    2048
#define D_    768
#define H_    12
#define HD    64
#define QKV_N (3*D_)      // 2304
#define M_    (B_*S_)     // 8192

// Scratch (no cudaMalloc allowed)
__device__ __half g_qh[M_ * QKV_N];   // qkv hi fp16 (Q pre-scaled by 0.125*log2e)
__device__ __half g_ql[M_ * QKV_N];   // qkv lo fp16
__device__ __half g_ah[M_ * D_];
__device__ __half g_al[M_ * D_];
__device__ __half g_bh[QKV_N * D_];   // weights single fp16 [N,K]

// ---------------------------------------------------------------------------
__device__ __forceinline__ uint32_t smem_u32(const void* p) {
    uint32_t a;
    asm("{ .reg .u64 t; cvta.to.shared.u64 t, %1; cvt.u32.u64 %0, t; }" : "=r"(a) : "l"(p));
    return a;
}

#define CP_ASYNC16(dst, src) \
    asm volatile("cp.async.cg.shared.global [%0], [%1], 16;" :: "r"(dst), "l"(src))
#define CP_COMMIT() asm volatile("cp.async.commit_group;" ::: "memory")
#define CP_WAIT0()  asm volatile("cp.async.wait_group 0;" ::: "memory")

#define LDM_X4(r, addr) \
    asm volatile("ldmatrix.sync.aligned.m8n8.x4.shared.b16 {%0,%1,%2,%3}, [%4];" \
        : "=r"((r)[0]), "=r"((r)[1]), "=r"((r)[2]), "=r"((r)[3]) : "r"(addr))
#define LDM_X4T(r, addr) \
    asm volatile("ldmatrix.sync.aligned.m8n8.x4.trans.shared.b16 {%0,%1,%2,%3}, [%4];" \
        : "=r"((r)[0]), "=r"((r)[1]), "=r"((r)[2]), "=r"((r)[3]) : "r"(addr))
#define LDM_X2(r, addr) \
    asm volatile("ldmatrix.sync.aligned.m8n8.x2.shared.b16 {%0,%1}, [%2];" \
        : "=r"((r)[0]), "=r"((r)[1]) : "r"(addr))
#define MMA_F16(d, a, b) \
    asm volatile("mma.sync.aligned.m16n8k16.row.col.f32.f16.f16.f32 " \
        "{%0,%1,%2,%3}, {%4,%5,%6,%7}, {%8,%9}, {%0,%1,%2,%3};" \
        : "+f"((d)[0]), "+f"((d)[1]), "+f"((d)[2]), "+f"((d)[3]) \
        : "r"((a)[0]), "r"((a)[1]), "r"((a)[2]), "r"((a)[3]), \
          "r"((b)[0]), "r"((b)[1]))
#define MMA_F16R(d, a, b0r, b1r) \
    asm volatile("mma.sync.aligned.m16n8k16.row.col.f32.f16.f16.f32 " \
        "{%0,%1,%2,%3}, {%4,%5,%6,%7}, {%8,%9}, {%0,%1,%2,%3};" \
        : "+f"((d)[0]), "+f"((d)[1]), "+f"((d)[2]), "+f"((d)[3]) \
        : "r"((a)[0]), "r"((a)[1]), "r"((a)[2]), "r"((a)[3]), \
          "r"(b0r), "r"(b1r))

__device__ __forceinline__ uint32_t pack_h2(float lo, float hi) {
    uint32_t r;
    asm("cvt.rn.f16x2.f32 %0, %1, %2;" : "=r"(r) : "f"(hi), "f"(lo));
    return r;
}

// store 4 consecutive fp32 values as fp16 hi/lo pairs
__device__ __forceinline__ void store_split4h(__half* ph, __half* pl, float4 v) {
    __half h0 = __float2half_rn(v.x), h1 = __float2half_rn(v.y);
    __half h2 = __float2half_rn(v.z), h3 = __float2half_rn(v.w);
    *(__half2*)(ph)     = __half2(h0, h1);
    *(__half2*)(ph + 2) = __half2(h2, h3);
    *(__half2*)(pl)     = __half2(
        __float2half_rn(v.x - __half2float(h0)),
        __float2half_rn(v.y - __half2float(h1)));
    *(__half2*)(pl + 2) = __half2(
        __float2half_rn(v.z - __half2float(h2)),
        __float2half_rn(v.w - __half2float(h3)));
}

// ---------------------------------------------------------------------------
__global__ void split_kernel(const float* __restrict__ in,
                             __half* __restrict__ hi,
                             __half* __restrict__ lo, int n4)
{
    int i = blockIdx.x * blockDim.x + threadIdx.x;
    if (i >= n4) return;
    float4 v = ((const float4*)in)[i];
    store_split4h(hi + 4 * (long)i, lo + 4 * (long)i, v);
}

// W[K,N] fp32 -> Bh[N,K] fp16 single (transpose + convert)
__global__ void transpose_cvt_kernel(const float* __restrict__ W,
                                     __half* __restrict__ Bh,
                                     int K, int N)
{
    __shared__ float t[32][33];
    int n0 = blockIdx.x * 32, k0 = blockIdx.y * 32;
    int tx = threadIdx.x, ty = threadIdx.y;
#pragma unroll
    for (int j = 0; j < 4; ++j)
        t[ty + j*8][tx] = W[(long)(k0 + ty + j*8) * N + n0 + tx];
    __syncthreads();
#pragma unroll
    for (int j = 0; j < 4; ++j)
        Bh[(long)(n0 + ty + j*8) * K + k0 + tx] = __float2half_rn(t[tx][ty + j*8]);
}

// ---------------------------------------------------------------------------
// fp16 2x1-term GEMM via mma.sync: C = (Ah+Al)[M,K] @ Bh[N,K]^T + bias
// cp.async double-buffered, 2 CTAs/SM.
// ---------------------------------------------------------------------------
#define LDA 40
#define G_ARR (128 * LDA * 2)        // 10240
#define G_STAGE (3 * G_ARR)          // 30720
#define G_SMEM (2 * G_STAGE)         // 61440

template<int SPLIT_OUT>
__global__ __launch_bounds__(256, 2)
void gemm_mma_kernel(const __half* __restrict__ Ah,
                     const __half* __restrict__ Al,
                     const __half* __restrict__ Bh,
                     const float* __restrict__ bias,
                     float* __restrict__ C,
                     __half* __restrict__ Ch,
                     __half* __restrict__ Cl,
                     int M, int N, int K, int scale_cols, float scale)
{
    extern __shared__ __half gsm[];
    const uint32_t sb = smem_u32(gsm);

    const int tid  = threadIdx.x;
    const int lane = tid & 31;
    const int wid  = tid >> 5;
    const int wm   = wid >> 2;
    const int wn   = wid & 3;
    const int m0   = blockIdx.y * 128;
    const int n0   = blockIdx.x * 128;
    const int KT   = K / 32;

    const __half* srcs[3] = {Ah, Al, Bh};
    const int row0s[3] = {m0, m0, n0};

    float acc[4][4][4];
#pragma unroll
    for (int i = 0; i < 4; ++i)
#pragma unroll
        for (int j = 0; j < 4; ++j)
#pragma unroll
            for (int r = 0; r < 4; ++r) acc[i][j][r] = 0.f;

    const int a_row = lane & 15;
    const int a_kb  = (lane >> 4) * 8;
    const int b_row = lane & 7;
    const int b_kb  = ((lane >> 3) & 1) * 8;

    auto cp_issue = [&](int kt, int stage) {
        const int k0 = kt * 32;
        const uint32_t sdst = sb + stage * G_STAGE;
#pragma unroll
        for (int t = 0; t < 3; ++t) {
            const __half* src = srcs[t];
            const int r0 = row0s[t];
#pragma unroll
            for (int it = 0; it < 2; ++it) {
                int chunk = tid + it * 256;
                int r = chunk >> 2, c = chunk & 3;
                uint32_t dst = sdst + t * G_ARR + (r * LDA + c * 8) * 2;
                CP_ASYNC16(dst, (const void*)&src[(long)(r0 + r) * K + k0 + c * 8]);
            }
        }
    };

    cp_issue(0, 0);
    CP_COMMIT();

    for (int kt = 0; kt < KT; ++kt) {
        CP_WAIT0();
        __syncthreads();
        if (kt + 1 < KT) { cp_issue(kt + 1, (kt + 1) & 1); CP_COMMIT(); }

        const uint32_t ub  = sb + (kt & 1) * G_STAGE;
        const uint32_t uAh = ub, uAl = ub + G_ARR, uBh = ub + 2 * G_ARR;

#pragma unroll
        for (int ks = 0; ks < 2; ++ks) {
            const int kc = ks * 16;
            uint32_t bh[4][2];
#pragma unroll
            for (int j = 0; j < 4; ++j) {
                uint32_t off = ((wn * 32 + j * 8 + b_row) * LDA + kc + b_kb) * 2;
                LDM_X2(bh[j], uBh + off);
            }
#pragma unroll
            for (int i = 0; i < 4; ++i) {
                uint32_t off = ((wm * 64 + i * 16 + a_row) * LDA + kc + a_kb) * 2;
                uint32_t ah[4], al[4];
                LDM_X4(ah, uAh + off);
                LDM_X4(al, uAl + off);
#pragma unroll
                for (int j = 0; j < 4; ++j) {
                    MMA_F16(acc[i][j], ah, bh[j]);
                    MMA_F16(acc[i][j], al, bh[j]);
                }
            }
        }
        __syncthreads();
    }

    const int qr = lane >> 2;
    const int qc = (lane & 3) * 2;
#pragma unroll
    for (int i = 0; i < 4; ++i) {
#pragma unroll
        for (int j = 0; j < 4; ++j) {
            int col = n0 + wn * 32 + j * 8 + qc;
            float b0 = __ldg(&bias[col]);
            float b1 = __ldg(&bias[col + 1]);
            long r0 = m0 + wm * 64 + i * 16 + qr;
            float v00 = acc[i][j][0] + b0, v01 = acc[i][j][1] + b1;
            float v10 = acc[i][j][2] + b0, v11 = acc[i][j][3] + b1;
            if (SPLIT_OUT) {
                float s = (col < scale_cols) ? scale : 1.f;
                v00 *= s; v01 *= s; v10 *= s; v11 *= s;
                __half h00 = __float2half_rn(v00), h01 = __float2half_rn(v01);
                __half h10 = __float2half_rn(v10), h11 = __float2half_rn(v11);
                *(__half2*)&Ch[r0 * N + col] = __half2(h00, h01);
                *(__half2*)&Cl[r0 * N + col] = __half2(
                    __float2half_rn(v00 - __half2float(h00)),
                    __float2half_rn(v01 - __half2float(h01)));
                *(__half2*)&Ch[(r0 + 8) * N + col] = __half2(h10, h11);
                *(__half2*)&Cl[(r0 + 8) * N + col] = __half2(
                    __float2half_rn(v10 - __half2float(h10)),
                    __float2half_rn(v11 - __half2float(h11)));
            } else {
                *(float2*)&C[r0 * N + col]       = make_float2(v00, v01);
                *(float2*)&C[(r0 + 8) * N + col] = make_float2(v10, v11);
            }
        }
    }
}

// ---------------------------------------------------------------------------
// Flash attention fp16: Q 2-term x K 1-term; P 1-term x V 2-term.
// 64-key half-tiles, cp.async double-buffered (Kh,Vh,Vl per stage), 2 CTAs/SM.
// ---------------------------------------------------------------------------
#define FA_LD 72
#define FA_QARR (128 * FA_LD * 2)     // 18432
#define FA_HARR (64 * FA_LD * 2)      // 9216
#define FA_KV0 (2 * FA_QARR)          // 36864
#define FA_STAGE (3 * FA_HARR)        // 27648
#define FA_SMEM (FA_KV0 + 2 * FA_STAGE)  // 92160 (x2 CTAs fits 228KB)

__global__ __launch_bounds__(256, 2)
void flash_mma_kernel(const __half* __restrict__ qh,
                      const __half* __restrict__ ql,
                      __half* __restrict__ oh,
                      __half* __restrict__ ol)
{
    extern __shared__ __half fsm[];
    const uint32_t sb = smem_u32(fsm);

    const int tid  = threadIdx.x;
    const int lane = tid & 31;
    const int wq   = tid >> 5;
    const int qt   = (int)gridDim.x - 1 - (int)blockIdx.x;   // big tiles first
    const int bh   = blockIdx.y;
    const int b    = bh / H_;
    const int h    = bh - b * H_;
    const int q0   = qt * 128;
    const long rowbase = (long)b * S_ * QKV_N + h * HD;

    // stage sources: Kh (hi), Vh (hi), Vl (lo)
    const __half* kvsrc[3] = {qh + D_, qh + 2 * D_, ql + 2 * D_};

    // prologue: Q hi/lo
    {
        const __half* qsrc[2] = {qh, ql};
#pragma unroll
        for (int t = 0; t < 2; ++t) {
#pragma unroll
            for (int it = 0; it < 4; ++it) {
                int chunk = tid + it * 256;
                int r = chunk >> 3, c = chunk & 7;
                uint32_t dst = sb + t * FA_QARR + (r * FA_LD + c * 8) * 2;
                CP_ASYNC16(dst, (const void*)&qsrc[t][rowbase + (long)(q0 + r) * QKV_N + c * 8]);
            }
        }
    }
    auto kv_issue = [&](int ht, int stage) {
        const int k0 = ht * 64;
        const uint32_t sdst = sb + FA_KV0 + stage * FA_STAGE;
#pragma unroll
        for (int t = 0; t < 3; ++t) {
#pragma unroll
            for (int it = 0; it < 2; ++it) {
                int chunk = tid + it * 256;
                int r = chunk >> 3, c = chunk & 7;
                uint32_t dst = sdst + t * FA_HARR + (r * FA_LD + c * 8) * 2;
                CP_ASYNC16(dst, (const void*)&kvsrc[t][rowbase + (long)(k0 + r) * QKV_N + c * 8]);
            }
        }
    };
    kv_issue(0, 0);
    CP_COMMIT();
    CP_WAIT0();
    __syncthreads();

    float o[8][4];
#pragma unroll
    for (int j = 0; j < 8; ++j)
#pragma unroll
        for (int r = 0; r < 4; ++r) o[j][r] = 0.f;
    float rm[2] = {-1e30f, -1e30f};
    float rl[2] = {0.f, 0.f};

    const int r0 = lane >> 2;
    const int c0 = (lane & 3) * 2;
    const int arow = wq * 16 + (lane & 15);
    const int acol = (lane >> 4) * 8;
    const int krow = (lane & 15);
    const int kcol = (lane >> 4) * 8;
    const int vr = (lane & 7) + ((lane >> 3) & 1) * 8;
    const int vc = (lane >> 4) * 8;

    const int nh = 2 * (qt + 1);
    for (int ht = 0; ht < nh; ++ht) {
        if (ht + 1 < nh) { kv_issue(ht + 1, (ht + 1) & 1); CP_COMMIT(); }

        const uint32_t ukv = sb + FA_KV0 + (ht & 1) * FA_STAGE;
        const uint32_t uKh = ukv;
        const uint32_t uVh = ukv + FA_HARR, uVl = ukv + 2 * FA_HARR;

        // S = Q K^T over 64 keys (Q 2-term, K 1-term)
        float sc[8][4];
#pragma unroll
        for (int j = 0; j < 8; ++j)
#pragma unroll
            for (int r = 0; r < 4; ++r) sc[j][r] = 0.f;

#pragma unroll
        for (int ks = 0; ks < 4; ++ks) {
            uint32_t qfh[4], qfl[4];
            uint32_t qoff = (arow * FA_LD + ks * 16 + acol) * 2;
            LDM_X4(qfh, sb + qoff);
            LDM_X4(qfl, sb + FA_QARR + qoff);
#pragma unroll
            for (int j2 = 0; j2 < 4; ++j2) {
                uint32_t off = ((j2 * 16 + krow) * FA_LD + ks * 16 + kcol) * 2;
                uint32_t kh[4];
                LDM_X4(kh, uKh + off);
                MMA_F16R(sc[2*j2],   qfh, kh[0], kh[2]);
                MMA_F16R(sc[2*j2+1], qfh, kh[1], kh[3]);
                MMA_F16R(sc[2*j2],   qfl, kh[0], kh[2]);
                MMA_F16R(sc[2*j2+1], qfl, kh[1], kh[3]);
            }
        }

        // causal mask (diagonal q-tile only)
        if ((ht >> 1) == qt) {
            int cbase = (ht & 1) * 64;
            int row0 = wq * 16 + r0;
            int row1 = row0 + 8;
#pragma unroll
            for (int j = 0; j < 8; ++j) {
                int col = cbase + j * 8 + c0;
                if (col     > row0) sc[j][0] = -1e30f;
                if (col + 1 > row0) sc[j][1] = -1e30f;
                if (col     > row1) sc[j][2] = -1e30f;
                if (col + 1 > row1) sc[j][3] = -1e30f;
            }
        }

        // online softmax (log2 domain; scores pre-scaled by log2e)
        float mx0 = -1e30f, mx1 = -1e30f;
#pragma unroll
        for (int j = 0; j < 8; ++j) {
            mx0 = fmaxf(mx0, fmaxf(sc[j][0], sc[j][1]));
            mx1 = fmaxf(mx1, fmaxf(sc[j][2], sc[j][3]));
        }
        mx0 = fmaxf(mx0, __shfl_xor_sync(0xffffffffu, mx0, 1));
        mx0 = fmaxf(mx0, __shfl_xor_sync(0xffffffffu, mx0, 2));
        mx1 = fmaxf(mx1, __shfl_xor_sync(0xffffffffu, mx1, 1));
        mx1 = fmaxf(mx1, __shfl_xor_sync(0xffffffffu, mx1, 2));

        float mn0 = fmaxf(rm[0], mx0);
        float mn1 = fmaxf(rm[1], mx1);
        float a0 = exp2f(rm[0] - mn0);
        float a1 = exp2f(rm[1] - mn1);
        rm[0] = mn0; rm[1] = mn1;

        float s0 = 0.f, s1 = 0.f;
#pragma unroll
        for (int j = 0; j < 8; ++j) {
            sc[j][0] = exp2f(sc[j][0] - mn0); s0 += sc[j][0];
            sc[j][1] = exp2f(sc[j][1] - mn0); s0 += sc[j][1];
            sc[j][2] = exp2f(sc[j][2] - mn1); s1 += sc[j][2];
            sc[j][3] = exp2f(sc[j][3] - mn1); s1 += sc[j][3];
        }
        s0 += __shfl_xor_sync(0xffffffffu, s0, 1);
        s0 += __shfl_xor_sync(0xffffffffu, s0, 2);
        s1 += __shfl_xor_sync(0xffffffffu, s1, 1);
        s1 += __shfl_xor_sync(0xffffffffu, s1, 2);
        rl[0] = rl[0] * a0 + s0;
        rl[1] = rl[1] * a1 + s1;
#pragma unroll
        for (int j = 0; j < 8; ++j) {
            o[j][0] *= a0; o[j][1] *= a0;
            o[j][2] *= a1; o[j][3] *= a1;
        }

        // O += P V  (P single fp16, V 2-term)
#pragma unroll
        for (int ks2 = 0; ks2 < 4; ++ks2) {
            uint32_t pf[4];
            pf[0] = pack_h2(sc[2*ks2][0],   sc[2*ks2][1]);
            pf[1] = pack_h2(sc[2*ks2][2],   sc[2*ks2][3]);
            pf[2] = pack_h2(sc[2*ks2+1][0], sc[2*ks2+1][1]);
            pf[3] = pack_h2(sc[2*ks2+1][2], sc[2*ks2+1][3]);
#pragma unroll
            for (int jp = 0; jp < 4; ++jp) {
                uint32_t voff = ((ks2 * 16 + vr) * FA_LD + jp * 16 + vc) * 2;
                uint32_t vh[4], vl[4];
                LDM_X4T(vh, uVh + voff);
                LDM_X4T(vl, uVl + voff);
                MMA_F16R(o[2*jp],   pf, vh[0], vh[1]);
                MMA_F16R(o[2*jp+1], pf, vh[2], vh[3]);
                MMA_F16R(o[2*jp],   pf, vl[0], vl[1]);
                MMA_F16R(o[2*jp+1], pf, vl[2], vl[3]);
            }
        }

        if (ht + 1 < nh) { CP_WAIT0(); __syncthreads(); }
    }

    // epilogue: normalize, split to fp16 hi/lo, store
    float inv0 = 1.f / rl[0];
    float inv1 = 1.f / rl[1];
    long grow0 = (long)b * S_ + q0 + wq * 16 + r0;
#pragma unroll
    for (int j = 0; j < 8; ++j) {
        int col = h * HD + j * 8 + c0;
        {
            float v0 = o[j][0] * inv0, v1 = o[j][1] * inv0;
            __half h0 = __float2half_rn(v0), h1 = __float2half_rn(v1);
            long off = grow0 * D_ + col;
            *(__half2*)&oh[off] = __half2(h0, h1);
            *(__half2*)&ol[off] = __half2(
                __float2half_rn(v0 - __half2float(h0)),
                __float2half_rn(v1 - __half2float(h1)));
        }
        {
            float v0 = o[j][2] * inv1, v1 = o[j][3] * inv1;
            __half h0 = __float2half_rn(v0), h1 = __float2half_rn(v1);
            long off = (grow0 + 8) * D_ + col;
            *(__half2*)&oh[off] = __half2(h0, h1);
            *(__half2*)&ol[off] = __half2(
                __float2half_rn(v0 - __half2float(h0)),
                __float2half_rn(v1 - __half2float(h1)));
        }
    }
}

// ---------------------------------------------------------------------------
extern "C" void kernel_launch(void* const* d_in, const int* in_sizes, int n_in,
                              void* d_out, int out_size)
{
    const float* x    = (const float*)d_in[0];
    const float* Wqkv = (const float*)d_in[1];
    const float* bqkv = (const float*)d_in[2];
    const float* Wp   = (const float*)d_in[3];
    const float* bp   = (const float*)d_in[4];
    float* out = (float*)d_out;

    __half *qh, *ql, *ah, *al, *bhp;
    cudaGetSymbolAddress((void**)&qh, g_qh);
    cudaGetSymbolAddress((void**)&ql, g_ql);
    cudaGetSymbolAddress((void**)&ah, g_ah);
    cudaGetSymbolAddress((void**)&al, g_al);
    cudaGetSymbolAddress((void**)&bhp, g_bh);

    cudaFuncSetAttribute(gemm_mma_kernel<1>,
                         cudaFuncAttributeMaxDynamicSharedMemorySize, G_SMEM);
    cudaFuncSetAttribute(gemm_mma_kernel<0>,
                         cudaFuncAttributeMaxDynamicSharedMemorySize, G_SMEM);
    cudaFuncSetAttribute(flash_mma_kernel,
                         cudaFuncAttributeMaxDynamicSharedMemorySize, FA_SMEM);

    const int n4 = M_ * D_ / 4;
    const float qscale = 0.125f * 1.44269504088896340736f;   // 1/sqrt(hd) * log2(e)

    // 1) split x (fp16 hi/lo); convert Wqkv -> [N,K] fp16; QKV GEMM -> fp16 hi/lo
    split_kernel<<<(n4 + 255) / 256, 256>>>(x, ah, al, n4);
    transpose_cvt_kernel<<<dim3(QKV_N / 32, D_ / 32), dim3(32, 8)>>>(Wqkv, bhp, D_, QKV_N);
    gemm_mma_kernel<1><<<dim3(QKV_N / 128, M_ / 128), 256, G_SMEM>>>(
        ah, al, bhp, bqkv, nullptr, qh, ql, M_, QKV_N, D_, D_, qscale);

    // 2) flash attention (fp16 in/out)
    flash_mma_kernel<<<dim3(S_ / 128, B_ * H_), 256, FA_SMEM>>>(qh, ql, ah, al);

    // 3) convert Wp; proj GEMM -> fp32 out
    transpose_cvt_kernel<<<dim3(D_ / 32, D_ / 32), dim3(32, 8)>>>(Wp, bhp, D_, D_);
    gemm_mma_kernel<0><<<dim3(D_ / 128, M_ / 128), 256, G_SMEM>>>(
        ah, al, bhp, bp, out, nullptr, nullptr, M_, D_, D_, 0, 1.f);
}

// round 13
// speedup vs baseline: 1.6092x; 1.1499x over previous
#include <cuda_runtime.h>
#include <cuda_fp16.h>
#include <cstdint>
#include <math.h>

#define B_    4
#define S_    2048
#define D_    768
#define H_    12
#define HD    64
#define QKV_N (3*D_)      // 2304
#define M_    (B_*S_)     // 8192

// Scratch (no cudaMalloc allowed)
__device__ __half g_qh[M_ * QKV_N];   // qkv hi fp16 (Q pre-scaled by 0.125*log2e)
__device__ __half g_ql[M_ * QKV_N];   // qkv lo fp16 (only Q region valid)
__device__ __half g_ah[M_ * D_];
__device__ __half g_al[M_ * D_];
__device__ __half g_bh[QKV_N * D_];   // weights single fp16 [N,K]

// ---------------------------------------------------------------------------
__device__ __forceinline__ uint32_t smem_u32(const void* p) {
    uint32_t a;
    asm("{ .reg .u64 t; cvta.to.shared.u64 t, %1; cvt.u32.u64 %0, t; }" : "=r"(a) : "l"(p));
    return a;
}

__device__ __forceinline__ float ex2f(float x) {
    float r;
    asm("ex2.approx.ftz.f32 %0, %1;" : "=f"(r) : "f"(x));
    return r;
}

#define CP_ASYNC16(dst, src) \
    asm volatile("cp.async.cg.shared.global [%0], [%1], 16;" :: "r"(dst), "l"(src))
#define CP_COMMIT() asm volatile("cp.async.commit_group;" ::: "memory")
#define CP_WAIT0()  asm volatile("cp.async.wait_group 0;" ::: "memory")

#define LDM_X4(r, addr) \
    asm volatile("ldmatrix.sync.aligned.m8n8.x4.shared.b16 {%0,%1,%2,%3}, [%4];" \
        : "=r"((r)[0]), "=r"((r)[1]), "=r"((r)[2]), "=r"((r)[3]) : "r"(addr))
#define LDM_X4T(r, addr) \
    asm volatile("ldmatrix.sync.aligned.m8n8.x4.trans.shared.b16 {%0,%1,%2,%3}, [%4];" \
        : "=r"((r)[0]), "=r"((r)[1]), "=r"((r)[2]), "=r"((r)[3]) : "r"(addr))
#define LDM_X2(r, addr) \
    asm volatile("ldmatrix.sync.aligned.m8n8.x2.shared.b16 {%0,%1}, [%2];" \
        : "=r"((r)[0]), "=r"((r)[1]) : "r"(addr))
#define MMA_F16(d, a, b) \
    asm volatile("mma.sync.aligned.m16n8k16.row.col.f32.f16.f16.f32 " \
        "{%0,%1,%2,%3}, {%4,%5,%6,%7}, {%8,%9}, {%0,%1,%2,%3};" \
        : "+f"((d)[0]), "+f"((d)[1]), "+f"((d)[2]), "+f"((d)[3]) \
        : "r"((a)[0]), "r"((a)[1]), "r"((a)[2]), "r"((a)[3]), \
          "r"((b)[0]), "r"((b)[1]))
#define MMA_F16R(d, a, b0r, b1r) \
    asm volatile("mma.sync.aligned.m16n8k16.row.col.f32.f16.f16.f32 " \
        "{%0,%1,%2,%3}, {%4,%5,%6,%7}, {%8,%9}, {%0,%1,%2,%3};" \
        : "+f"((d)[0]), "+f"((d)[1]), "+f"((d)[2]), "+f"((d)[3]) \
        : "r"((a)[0]), "r"((a)[1]), "r"((a)[2]), "r"((a)[3]), \
          "r"(b0r), "r"(b1r))

__device__ __forceinline__ uint32_t pack_h2(float lo, float hi) {
    uint32_t r;
    asm("cvt.rn.f16x2.f32 %0, %1, %2;" : "=r"(r) : "f"(hi), "f"(lo));
    return r;
}

__device__ __forceinline__ void store_split4h(__half* ph, __half* pl, float4 v) {
    __half h0 = __float2half_rn(v.x), h1 = __float2half_rn(v.y);
    __half h2 = __float2half_rn(v.z), h3 = __float2half_rn(v.w);
    *(__half2*)(ph)     = __half2(h0, h1);
    *(__half2*)(ph + 2) = __half2(h2, h3);
    *(__half2*)(pl)     = __half2(
        __float2half_rn(v.x - __half2float(h0)),
        __float2half_rn(v.y - __half2float(h1)));
    *(__half2*)(pl + 2) = __half2(
        __float2half_rn(v.z - __half2float(h2)),
        __float2half_rn(v.w - __half2float(h3)));
}

// ---------------------------------------------------------------------------
__global__ void split_kernel(const float* __restrict__ in,
                             __half* __restrict__ hi,
                             __half* __restrict__ lo, int n4)
{
    int i = blockIdx.x * blockDim.x + threadIdx.x;
    if (i >= n4) return;
    float4 v = ((const float4*)in)[i];
    store_split4h(hi + 4 * (long)i, lo + 4 * (long)i, v);
}

// W[K,N] fp32 -> Bh[N,K] fp16 single (transpose + convert)
__global__ void transpose_cvt_kernel(const float* __restrict__ W,
                                     __half* __restrict__ Bh,
                                     int K, int N)
{
    __shared__ float t[32][33];
    int n0 = blockIdx.x * 32, k0 = blockIdx.y * 32;
    int tx = threadIdx.x, ty = threadIdx.y;
#pragma unroll
    for (int j = 0; j < 4; ++j)
        t[ty + j*8][tx] = W[(long)(k0 + ty + j*8) * N + n0 + tx];
    __syncthreads();
#pragma unroll
    for (int j = 0; j < 4; ++j)
        Bh[(long)(n0 + ty + j*8) * K + k0 + tx] = __float2half_rn(t[tx][ty + j*8]);
}

// ---------------------------------------------------------------------------
// fp16 2x1-term GEMM: C = (Ah+Al)[M,K] @ Bh[N,K]^T + bias
// SPLIT_OUT: hi always written; lo written only for col < lo_cols.
// ---------------------------------------------------------------------------
#define LDA 40
#define G_ARR (128 * LDA * 2)        // 10240
#define G_STAGE (3 * G_ARR)          // 30720
#define G_SMEM (2 * G_STAGE)         // 61440

template<int SPLIT_OUT>
__global__ __launch_bounds__(256, 2)
void gemm_mma_kernel(const __half* __restrict__ Ah,
                     const __half* __restrict__ Al,
                     const __half* __restrict__ Bh,
                     const float* __restrict__ bias,
                     float* __restrict__ C,
                     __half* __restrict__ Ch,
                     __half* __restrict__ Cl,
                     int M, int N, int K, int scale_cols, float scale, int lo_cols)
{
    extern __shared__ __half gsm[];
    const uint32_t sb = smem_u32(gsm);

    const int tid  = threadIdx.x;
    const int lane = tid & 31;
    const int wid  = tid >> 5;
    const int wm   = wid >> 2;
    const int wn   = wid & 3;
    const int m0   = blockIdx.y * 128;
    const int n0   = blockIdx.x * 128;
    const int KT   = K / 32;

    const __half* srcs[3] = {Ah, Al, Bh};
    const int row0s[3] = {m0, m0, n0};

    float acc[4][4][4];
#pragma unroll
    for (int i = 0; i < 4; ++i)
#pragma unroll
        for (int j = 0; j < 4; ++j)
#pragma unroll
            for (int r = 0; r < 4; ++r) acc[i][j][r] = 0.f;

    const int a_row = lane & 15;
    const int a_kb  = (lane >> 4) * 8;
    const int b_row = lane & 7;
    const int b_kb  = ((lane >> 3) & 1) * 8;

    auto cp_issue = [&](int kt, int stage) {
        const int k0 = kt * 32;
        const uint32_t sdst = sb + stage * G_STAGE;
#pragma unroll
        for (int t = 0; t < 3; ++t) {
            const __half* src = srcs[t];
            const int r0 = row0s[t];
#pragma unroll
            for (int it = 0; it < 2; ++it) {
                int chunk = tid + it * 256;
                int r = chunk >> 2, c = chunk & 3;
                uint32_t dst = sdst + t * G_ARR + (r * LDA + c * 8) * 2;
                CP_ASYNC16(dst, (const void*)&src[(long)(r0 + r) * K + k0 + c * 8]);
            }
        }
    };

    cp_issue(0, 0);
    CP_COMMIT();

    for (int kt = 0; kt < KT; ++kt) {
        CP_WAIT0();
        __syncthreads();
        if (kt + 1 < KT) { cp_issue(kt + 1, (kt + 1) & 1); CP_COMMIT(); }

        const uint32_t ub  = sb + (kt & 1) * G_STAGE;
        const uint32_t uAh = ub, uAl = ub + G_ARR, uBh = ub + 2 * G_ARR;

#pragma unroll
        for (int ks = 0; ks < 2; ++ks) {
            const int kc = ks * 16;
            uint32_t bh[4][2];
#pragma unroll
            for (int j = 0; j < 4; ++j) {
                uint32_t off = ((wn * 32 + j * 8 + b_row) * LDA + kc + b_kb) * 2;
                LDM_X2(bh[j], uBh + off);
            }
#pragma unroll
            for (int i = 0; i < 4; ++i) {
                uint32_t off = ((wm * 64 + i * 16 + a_row) * LDA + kc + a_kb) * 2;
                uint32_t ah[4], al[4];
                LDM_X4(ah, uAh + off);
                LDM_X4(al, uAl + off);
#pragma unroll
                for (int j = 0; j < 4; ++j) {
                    MMA_F16(acc[i][j], ah, bh[j]);
                    MMA_F16(acc[i][j], al, bh[j]);
                }
            }
        }
        __syncthreads();
    }

    const int qr = lane >> 2;
    const int qc = (lane & 3) * 2;
#pragma unroll
    for (int i = 0; i < 4; ++i) {
#pragma unroll
        for (int j = 0; j < 4; ++j) {
            int col = n0 + wn * 32 + j * 8 + qc;
            float b0 = __ldg(&bias[col]);
            float b1 = __ldg(&bias[col + 1]);
            long r0 = m0 + wm * 64 + i * 16 + qr;
            float v00 = acc[i][j][0] + b0, v01 = acc[i][j][1] + b1;
            float v10 = acc[i][j][2] + b0, v11 = acc[i][j][3] + b1;
            if (SPLIT_OUT) {
                float s = (col < scale_cols) ? scale : 1.f;
                v00 *= s; v01 *= s; v10 *= s; v11 *= s;
                __half h00 = __float2half_rn(v00), h01 = __float2half_rn(v01);
                __half h10 = __float2half_rn(v10), h11 = __float2half_rn(v11);
                *(__half2*)&Ch[r0 * N + col]       = __half2(h00, h01);
                *(__half2*)&Ch[(r0 + 8) * N + col] = __half2(h10, h11);
                if (col < lo_cols) {
                    *(__half2*)&Cl[r0 * N + col] = __half2(
                        __float2half_rn(v00 - __half2float(h00)),
                        __float2half_rn(v01 - __half2float(h01)));
                    *(__half2*)&Cl[(r0 + 8) * N + col] = __half2(
                        __float2half_rn(v10 - __half2float(h10)),
                        __float2half_rn(v11 - __half2float(h11)));
                }
            } else {
                *(float2*)&C[r0 * N + col]       = make_float2(v00, v01);
                *(float2*)&C[(r0 + 8) * N + col] = make_float2(v10, v11);
            }
        }
    }
}

// ---------------------------------------------------------------------------
// Flash attention fp16: Q 2-term x K 1-term; P 1-term x V 1-term.
// 128-key tiles, cp.async double-buffered (Kh,Vh per stage), 2 CTAs/SM.
// ---------------------------------------------------------------------------
#define FA_LD 72
#define FA_ARR (128 * FA_LD * 2)      // 18432
#define FA_KV0 (2 * FA_ARR)           // Q hi+lo: 36864
#define FA_STAGE (2 * FA_ARR)         // K,V: 36864
#define FA_SMEM (FA_KV0 + 2 * FA_STAGE)  // 110592 (x2 CTAs = 221KB)

__global__ __launch_bounds__(256, 2)
void flash_mma_kernel(const __half* __restrict__ qh,
                      const __half* __restrict__ ql,
                      __half* __restrict__ oh,
                      __half* __restrict__ ol)
{
    extern __shared__ __half fsm[];
    const uint32_t sb = smem_u32(fsm);

    const int tid  = threadIdx.x;
    const int lane = tid & 31;
    const int wq   = tid >> 5;
    const int qt   = (int)gridDim.x - 1 - (int)blockIdx.x;   // big tiles first
    const int bh   = blockIdx.y;
    const int b    = bh / H_;
    const int h    = bh - b * H_;
    const int q0   = qt * 128;
    const long rowbase = (long)b * S_ * QKV_N + h * HD;

    const __half* kvsrc[2] = {qh + D_, qh + 2 * D_};   // K hi, V hi

    // prologue: Q hi/lo
    {
        const __half* qsrc[2] = {qh, ql};
#pragma unroll
        for (int t = 0; t < 2; ++t) {
#pragma unroll
            for (int it = 0; it < 4; ++it) {
                int chunk = tid + it * 256;
                int r = chunk >> 3, c = chunk & 7;
                uint32_t dst = sb + t * FA_ARR + (r * FA_LD + c * 8) * 2;
                CP_ASYNC16(dst, (const void*)&qsrc[t][rowbase + (long)(q0 + r) * QKV_N + c * 8]);
            }
        }
    }
    auto kv_issue = [&](int kt, int stage) {
        const int k0 = kt * 128;
        const uint32_t sdst = sb + FA_KV0 + stage * FA_STAGE;
#pragma unroll
        for (int t = 0; t < 2; ++t) {
#pragma unroll
            for (int it = 0; it < 4; ++it) {
                int chunk = tid + it * 256;
                int r = chunk >> 3, c = chunk & 7;
                uint32_t dst = sdst + t * FA_ARR + (r * FA_LD + c * 8) * 2;
                CP_ASYNC16(dst, (const void*)&kvsrc[t][rowbase + (long)(k0 + r) * QKV_N + c * 8]);
            }
        }
    };
    kv_issue(0, 0);
    CP_COMMIT();
    CP_WAIT0();
    __syncthreads();

    float o[8][4];
#pragma unroll
    for (int j = 0; j < 8; ++j)
#pragma unroll
        for (int r = 0; r < 4; ++r) o[j][r] = 0.f;
    float rm[2] = {-1e30f, -1e30f};
    float rl[2] = {0.f, 0.f};

    const int r0 = lane >> 2;
    const int c0 = (lane & 3) * 2;
    const int arow = wq * 16 + (lane & 15);
    const int acol = (lane >> 4) * 8;
    const int krow = (lane & 15);
    const int kcol = (lane >> 4) * 8;
    const int vr = (lane & 7) + ((lane >> 3) & 1) * 8;
    const int vc = (lane >> 4) * 8;

    for (int kt = 0; kt <= qt; ++kt) {
        if (kt < qt) { kv_issue(kt + 1, (kt + 1) & 1); CP_COMMIT(); }

        const uint32_t ukv = sb + FA_KV0 + (kt & 1) * FA_STAGE;
        const uint32_t uKh = ukv, uVh = ukv + FA_ARR;

        // S = Q K^T over 128 keys (Q 2-term, K 1-term)
        float sc[16][4];
#pragma unroll
        for (int j = 0; j < 16; ++j)
#pragma unroll
            for (int r = 0; r < 4; ++r) sc[j][r] = 0.f;

#pragma unroll
        for (int ks = 0; ks < 4; ++ks) {
            uint32_t qfh[4], qfl[4];
            uint32_t qoff = (arow * FA_LD + ks * 16 + acol) * 2;
            LDM_X4(qfh, sb + qoff);
            LDM_X4(qfl, sb + FA_ARR + qoff);
#pragma unroll
            for (int j2 = 0; j2 < 8; ++j2) {
                uint32_t off = ((j2 * 16 + krow) * FA_LD + ks * 16 + kcol) * 2;
                uint32_t kh[4];
                LDM_X4(kh, uKh + off);
                MMA_F16R(sc[2*j2],   qfh, kh[0], kh[2]);
                MMA_F16R(sc[2*j2+1], qfh, kh[1], kh[3]);
                MMA_F16R(sc[2*j2],   qfl, kh[0], kh[2]);
                MMA_F16R(sc[2*j2+1], qfl, kh[1], kh[3]);
            }
        }

        // causal mask (diagonal tile)
        if (kt == qt) {
            int row0 = wq * 16 + r0;
            int row1 = row0 + 8;
#pragma unroll
            for (int j = 0; j < 16; ++j) {
                int col = j * 8 + c0;
                if (col     > row0) sc[j][0] = -1e30f;
                if (col + 1 > row0) sc[j][1] = -1e30f;
                if (col     > row1) sc[j][2] = -1e30f;
                if (col + 1 > row1) sc[j][3] = -1e30f;
            }
        }

        // online softmax (log2 domain; scores pre-scaled by log2e)
        float mx0 = -1e30f, mx1 = -1e30f;
#pragma unroll
        for (int j = 0; j < 16; ++j) {
            mx0 = fmaxf(mx0, fmaxf(sc[j][0], sc[j][1]));
            mx1 = fmaxf(mx1, fmaxf(sc[j][2], sc[j][3]));
        }
        mx0 = fmaxf(mx0, __shfl_xor_sync(0xffffffffu, mx0, 1));
        mx0 = fmaxf(mx0, __shfl_xor_sync(0xffffffffu, mx0, 2));
        mx1 = fmaxf(mx1, __shfl_xor_sync(0xffffffffu, mx1, 1));
        mx1 = fmaxf(mx1, __shfl_xor_sync(0xffffffffu, mx1, 2));

        float mn0 = fmaxf(rm[0], mx0);
        float mn1 = fmaxf(rm[1], mx1);
        float a0 = ex2f(rm[0] - mn0);
        float a1 = ex2f(rm[1] - mn1);
        rm[0] = mn0; rm[1] = mn1;

        float s0 = 0.f, s1 = 0.f;
#pragma unroll
        for (int j = 0; j < 16; ++j) {
            sc[j][0] = ex2f(sc[j][0] - mn0); s0 += sc[j][0];
            sc[j][1] = ex2f(sc[j][1] - mn0); s0 += sc[j][1];
            sc[j][2] = ex2f(sc[j][2] - mn1); s1 += sc[j][2];
            sc[j][3] = ex2f(sc[j][3] - mn1); s1 += sc[j][3];
        }
        s0 += __shfl_xor_sync(0xffffffffu, s0, 1);
        s0 += __shfl_xor_sync(0xffffffffu, s0, 2);
        s1 += __shfl_xor_sync(0xffffffffu, s1, 1);
        s1 += __shfl_xor_sync(0xffffffffu, s1, 2);
        rl[0] = rl[0] * a0 + s0;
        rl[1] = rl[1] * a1 + s1;
#pragma unroll
        for (int j = 0; j < 8; ++j) {
            o[j][0] *= a0; o[j][1] *= a0;
            o[j][2] *= a1; o[j][3] *= a1;
        }

        // O += P V  (P single fp16, V single fp16)
#pragma unroll
        for (int ks2 = 0; ks2 < 8; ++ks2) {
            uint32_t pf[4];
            pf[0] = pack_h2(sc[2*ks2][0],   sc[2*ks2][1]);
            pf[1] = pack_h2(sc[2*ks2][2],   sc[2*ks2][3]);
            pf[2] = pack_h2(sc[2*ks2+1][0], sc[2*ks2+1][1]);
            pf[3] = pack_h2(sc[2*ks2+1][2], sc[2*ks2+1][3]);
#pragma unroll
            for (int jp = 0; jp < 4; ++jp) {
                uint32_t voff = ((ks2 * 16 + vr) * FA_LD + jp * 16 + vc) * 2;
                uint32_t vh[4];
                LDM_X4T(vh, uVh + voff);
                MMA_F16R(o[2*jp],   pf, vh[0], vh[1]);
                MMA_F16R(o[2*jp+1], pf, vh[2], vh[3]);
            }
        }

        if (kt < qt) { CP_WAIT0(); __syncthreads(); }
    }

    // epilogue: normalize, split to fp16 hi/lo, store
    float inv0 = 1.f / rl[0];
    float inv1 = 1.f / rl[1];
    long grow0 = (long)b * S_ + q0 + wq * 16 + r0;
#pragma unroll
    for (int j = 0; j < 8; ++j) {
        int col = h * HD + j * 8 + c0;
        {
            float v0 = o[j][0] * inv0, v1 = o[j][1] * inv0;
            __half h0 = __float2half_rn(v0), h1 = __float2half_rn(v1);
            long off = grow0 * D_ + col;
            *(__half2*)&oh[off] = __half2(h0, h1);
            *(__half2*)&ol[off] = __half2(
                __float2half_rn(v0 - __half2float(h0)),
                __float2half_rn(v1 - __half2float(h1)));
        }
        {
            float v0 = o[j][2] * inv1, v1 = o[j][3] * inv1;
            __half h0 = __float2half_rn(v0), h1 = __float2half_rn(v1);
            long off = (grow0 + 8) * D_ + col;
            *(__half2*)&oh[off] = __half2(h0, h1);
            *(__half2*)&ol[off] = __half2(
                __float2half_rn(v0 - __half2float(h0)),
                __float2half_rn(v1 - __half2float(h1)));
        }
    }
}

// ---------------------------------------------------------------------------
extern "C" void kernel_launch(void* const* d_in, const int* in_sizes, int n_in,
                              void* d_out, int out_size)
{
    const float* x    = (const float*)d_in[0];
    const float* Wqkv = (const float*)d_in[1];
    const float* bqkv = (const float*)d_in[2];
    const float* Wp   = (const float*)d_in[3];
    const float* bp   = (const float*)d_in[4];
    float* out = (float*)d_out;

    __half *qh, *ql, *ah, *al, *bhp;
    cudaGetSymbolAddress((void**)&qh, g_qh);
    cudaGetSymbolAddress((void**)&ql, g_ql);
    cudaGetSymbolAddress((void**)&ah, g_ah);
    cudaGetSymbolAddress((void**)&al, g_al);
    cudaGetSymbolAddress((void**)&bhp, g_bh);

    cudaFuncSetAttribute(gemm_mma_kernel<1>,
                         cudaFuncAttributeMaxDynamicSharedMemorySize, G_SMEM);
    cudaFuncSetAttribute(gemm_mma_kernel<0>,
                         cudaFuncAttributeMaxDynamicSharedMemorySize, G_SMEM);
    cudaFuncSetAttribute(flash_mma_kernel,
                         cudaFuncAttributeMaxDynamicSharedMemorySize, FA_SMEM);

    const int n4 = M_ * D_ / 4;
    const float qscale = 0.125f * 1.44269504088896340736f;   // 1/sqrt(hd) * log2(e)

    // 1) split x; convert Wqkv; QKV GEMM -> fp16 hi (+lo for Q cols only)
    split_kernel<<<(n4 + 255) / 256, 256>>>(x, ah, al, n4);
    transpose_cvt_kernel<<<dim3(QKV_N / 32, D_ / 32), dim3(32, 8)>>>(Wqkv, bhp, D_, QKV_N);
    gemm_mma_kernel<1><<<dim3(QKV_N / 128, M_ / 128), 256, G_SMEM>>>(
        ah, al, bhp, bqkv, nullptr, qh, ql, M_, QKV_N, D_, D_, qscale, D_);

    // 2) flash attention (fp16 in/out)
    flash_mma_kernel<<<dim3(S_ / 128, B_ * H_), 256, FA_SMEM>>>(qh, ql, ah, al);

    // 3) convert Wp; proj GEMM -> fp32 out
    transpose_cvt_kernel<<<dim3(D_ / 32, D_ / 32), dim3(32, 8)>>>(Wp, bhp, D_, D_);
    gemm_mma_kernel<0><<<dim3(D_ / 128, M_ / 128), 256, G_SMEM>>>(
        ah, al, bhp, bp, out, nullptr, nullptr, M_, D_, D_, 0, 1.f, 0);
}

// round 15
// speedup vs baseline: 1.6845x; 1.0468x over previous
#include <cuda_runtime.h>
#include <cuda_fp16.h>
#include <cstdint>
#include <math.h>

#define B_    4
#define S_    2048
#define D_    768
#define H_    12
#define HD    64
#define QKV_N (3*D_)      // 2304
#define M_    (B_*S_)     // 8192

// Scratch (no cudaMalloc allowed)
__device__ __half g_qh[M_ * QKV_N];   // qkv hi fp16 (Q pre-scaled by 0.125*log2e)
__device__ __half g_ql[M_ * QKV_N];   // qkv lo fp16 (only Q region valid)
__device__ __half g_ah[M_ * D_];
__device__ __half g_al[M_ * D_];
__device__ __half g_bh[QKV_N * D_];   // weights single fp16 [N,K]

// ---------------------------------------------------------------------------
__device__ __forceinline__ uint32_t smem_u32(const void* p) {
    uint32_t a;
    asm("{ .reg .u64 t; cvta.to.shared.u64 t, %1; cvt.u32.u64 %0, t; }" : "=r"(a) : "l"(p));
    return a;
}

__device__ __forceinline__ float ex2f(float x) {
    float r;
    asm("ex2.approx.ftz.f32 %0, %1;" : "=f"(r) : "f"(x));
    return r;
}

#define CP_ASYNC16(dst, src) \
    asm volatile("cp.async.cg.shared.global [%0], [%1], 16;" :: "r"(dst), "l"(src))
#define CP_COMMIT() asm volatile("cp.async.commit_group;" ::: "memory")
#define CP_WAIT0()  asm volatile("cp.async.wait_group 0;" ::: "memory")

#define LDM_X4(r, addr) \
    asm volatile("ldmatrix.sync.aligned.m8n8.x4.shared.b16 {%0,%1,%2,%3}, [%4];" \
        : "=r"((r)[0]), "=r"((r)[1]), "=r"((r)[2]), "=r"((r)[3]) : "r"(addr))
#define LDM_X4T(r, addr) \
    asm volatile("ldmatrix.sync.aligned.m8n8.x4.trans.shared.b16 {%0,%1,%2,%3}, [%4];" \
        : "=r"((r)[0]), "=r"((r)[1]), "=r"((r)[2]), "=r"((r)[3]) : "r"(addr))
#define LDM_X2(r, addr) \
    asm volatile("ldmatrix.sync.aligned.m8n8.x2.shared.b16 {%0,%1}, [%2];" \
        : "=r"((r)[0]), "=r"((r)[1]) : "r"(addr))
#define MMA_F16(d, a, b) \
    asm volatile("mma.sync.aligned.m16n8k16.row.col.f32.f16.f16.f32 " \
        "{%0,%1,%2,%3}, {%4,%5,%6,%7}, {%8,%9}, {%0,%1,%2,%3};" \
        : "+f"((d)[0]), "+f"((d)[1]), "+f"((d)[2]), "+f"((d)[3]) \
        : "r"((a)[0]), "r"((a)[1]), "r"((a)[2]), "r"((a)[3]), \
          "r"((b)[0]), "r"((b)[1]))
#define MMA_F16R(d, a, b0r, b1r) \
    asm volatile("mma.sync.aligned.m16n8k16.row.col.f32.f16.f16.f32 " \
        "{%0,%1,%2,%3}, {%4,%5,%6,%7}, {%8,%9}, {%0,%1,%2,%3};" \
        : "+f"((d)[0]), "+f"((d)[1]), "+f"((d)[2]), "+f"((d)[3]) \
        : "r"((a)[0]), "r"((a)[1]), "r"((a)[2]), "r"((a)[3]), \
          "r"(b0r), "r"(b1r))

__device__ __forceinline__ uint32_t pack_h2(float lo, float hi) {
    uint32_t r;
    asm("cvt.rn.f16x2.f32 %0, %1, %2;" : "=r"(r) : "f"(hi), "f"(lo));
    return r;
}

__device__ __forceinline__ void store_split4h(__half* ph, __half* pl, float4 v) {
    __half h0 = __float2half_rn(v.x), h1 = __float2half_rn(v.y);
    __half h2 = __float2half_rn(v.z), h3 = __float2half_rn(v.w);
    *(__half2*)(ph)     = __half2(h0, h1);
    *(__half2*)(ph + 2) = __half2(h2, h3);
    *(__half2*)(pl)     = __half2(
        __float2half_rn(v.x - __half2float(h0)),
        __float2half_rn(v.y - __half2float(h1)));
    *(__half2*)(pl + 2) = __half2(
        __float2half_rn(v.z - __half2float(h2)),
        __float2half_rn(v.w - __half2float(h3)));
}

// ---------------------------------------------------------------------------
__global__ void split_kernel(const float* __restrict__ in,
                             __half* __restrict__ hi,
                             __half* __restrict__ lo, int n4)
{
    int i = blockIdx.x * blockDim.x + threadIdx.x;
    if (i >= n4) return;
    float4 v = ((const float4*)in)[i];
    store_split4h(hi + 4 * (long)i, lo + 4 * (long)i, v);
}

// W[K,N] fp32 -> Bh[N,K] fp16 single (transpose + convert)
__global__ void transpose_cvt_kernel(const float* __restrict__ W,
                                     __half* __restrict__ Bh,
                                     int K, int N)
{
    __shared__ float t[32][33];
    int n0 = blockIdx.x * 32, k0 = blockIdx.y * 32;
    int tx = threadIdx.x, ty = threadIdx.y;
#pragma unroll
    for (int j = 0; j < 4; ++j)
        t[ty + j*8][tx] = W[(long)(k0 + ty + j*8) * N + n0 + tx];
    __syncthreads();
#pragma unroll
    for (int j = 0; j < 4; ++j)
        Bh[(long)(n0 + ty + j*8) * K + k0 + tx] = __float2half_rn(t[tx][ty + j*8]);
}

// ---------------------------------------------------------------------------
// fp16 GEMM: C = A[M,K] @ Bh[N,K]^T + bias.
// A is 2-term (Ah+Al) for output-column blocks with n0 < a_lo_ncols, else
// 1-term (Ah only). SPLIT_OUT: hi always; lo written for col < lo_cols.
// ---------------------------------------------------------------------------
#define LDA 40
#define G_ARR (128 * LDA * 2)        // 10240
#define G_STAGE (3 * G_ARR)          // 30720
#define G_SMEM (2 * G_STAGE)         // 61440

template<int SPLIT_OUT>
__global__ __launch_bounds__(256, 2)
void gemm_mma_kernel(const __half* __restrict__ Ah,
                     const __half* __restrict__ Al,
                     const __half* __restrict__ Bh,
                     const float* __restrict__ bias,
                     float* __restrict__ C,
                     __half* __restrict__ Ch,
                     __half* __restrict__ Cl,
                     int M, int N, int K, int scale_cols, float scale,
                     int lo_cols, int a_lo_ncols)
{
    extern __shared__ __half gsm[];
    const uint32_t sb = smem_u32(gsm);

    const int tid  = threadIdx.x;
    const int lane = tid & 31;
    const int wid  = tid >> 5;
    const int wm   = wid >> 2;
    const int wn   = wid & 3;
    const int m0   = blockIdx.y * 128;
    const int n0   = blockIdx.x * 128;
    const int KT   = K / 32;
    const bool two = (n0 < a_lo_ncols);   // uniform per CTA

    float acc[4][4][4];
#pragma unroll
    for (int i = 0; i < 4; ++i)
#pragma unroll
        for (int j = 0; j < 4; ++j)
#pragma unroll
            for (int r = 0; r < 4; ++r) acc[i][j][r] = 0.f;

    const int a_row = lane & 15;
    const int a_kb  = (lane >> 4) * 8;
    const int b_row = lane & 7;
    const int b_kb  = ((lane >> 3) & 1) * 8;

    auto cp_issue = [&](int kt, int stage) {
        const int k0 = kt * 32;
        const uint32_t sdst = sb + stage * G_STAGE;
#pragma unroll
        for (int it = 0; it < 2; ++it) {
            int chunk = tid + it * 256;
            int r = chunk >> 2, c = chunk & 3;
            uint32_t soff = (r * LDA + c * 8) * 2;
            CP_ASYNC16(sdst + soff, (const void*)&Ah[(long)(m0 + r) * K + k0 + c * 8]);
            if (two)
                CP_ASYNC16(sdst + G_ARR + soff, (const void*)&Al[(long)(m0 + r) * K + k0 + c * 8]);
            CP_ASYNC16(sdst + 2 * G_ARR + soff, (const void*)&Bh[(long)(n0 + r) * K + k0 + c * 8]);
        }
    };

    cp_issue(0, 0);
    CP_COMMIT();

    for (int kt = 0; kt < KT; ++kt) {
        CP_WAIT0();
        __syncthreads();
        if (kt + 1 < KT) { cp_issue(kt + 1, (kt + 1) & 1); CP_COMMIT(); }

        const uint32_t ub  = sb + (kt & 1) * G_STAGE;
        const uint32_t uAh = ub, uAl = ub + G_ARR, uBh = ub + 2 * G_ARR;

#pragma unroll
        for (int ks = 0; ks < 2; ++ks) {
            const int kc = ks * 16;
            uint32_t bh[4][2];
#pragma unroll
            for (int j = 0; j < 4; ++j) {
                uint32_t off = ((wn * 32 + j * 8 + b_row) * LDA + kc + b_kb) * 2;
                LDM_X2(bh[j], uBh + off);
            }
#pragma unroll
            for (int i = 0; i < 4; ++i) {
                uint32_t off = ((wm * 64 + i * 16 + a_row) * LDA + kc + a_kb) * 2;
                uint32_t ah[4];
                LDM_X4(ah, uAh + off);
#pragma unroll
                for (int j = 0; j < 4; ++j)
                    MMA_F16(acc[i][j], ah, bh[j]);
                if (two) {
                    uint32_t al[4];
                    LDM_X4(al, uAl + off);
#pragma unroll
                    for (int j = 0; j < 4; ++j)
                        MMA_F16(acc[i][j], al, bh[j]);
                }
            }
        }
        __syncthreads();
    }

    const int qr = lane >> 2;
    const int qc = (lane & 3) * 2;
#pragma unroll
    for (int i = 0; i < 4; ++i) {
#pragma unroll
        for (int j = 0; j < 4; ++j) {
            int col = n0 + wn * 32 + j * 8 + qc;
            float b0 = __ldg(&bias[col]);
            float b1 = __ldg(&bias[col + 1]);
            long r0 = m0 + wm * 64 + i * 16 + qr;
            float v00 = acc[i][j][0] + b0, v01 = acc[i][j][1] + b1;
            float v10 = acc[i][j][2] + b0, v11 = acc[i][j][3] + b1;
            if (SPLIT_OUT) {
                float s = (col < scale_cols) ? scale : 1.f;
                v00 *= s; v01 *= s; v10 *= s; v11 *= s;
                __half h00 = __float2half_rn(v00), h01 = __float2half_rn(v01);
                __half h10 = __float2half_rn(v10), h11 = __float2half_rn(v11);
                *(__half2*)&Ch[r0 * N + col]       = __half2(h00, h01);
                *(__half2*)&Ch[(r0 + 8) * N + col] = __half2(h10, h11);
                if (col < lo_cols) {
                    *(__half2*)&Cl[r0 * N + col] = __half2(
                        __float2half_rn(v00 - __half2float(h00)),
                        __float2half_rn(v01 - __half2float(h01)));
                    *(__half2*)&Cl[(r0 + 8) * N + col] = __half2(
                        __float2half_rn(v10 - __half2float(h10)),
                        __float2half_rn(v11 - __half2float(h11)));
                }
            } else {
                *(float2*)&C[r0 * N + col]       = make_float2(v00, v01);
                *(float2*)&C[(r0 + 8) * N + col] = make_float2(v10, v11);
            }
        }
    }
}

// ---------------------------------------------------------------------------
// Flash attention fp16: Q 2-term x K 1-term; P 1-term x V 1-term.
// 128-key tiles, cp.async double-buffered, 2 CTAs/SM. Output hi-only fp16.
// ---------------------------------------------------------------------------
#define FA_LD 72
#define FA_ARR (128 * FA_LD * 2)      // 18432
#define FA_KV0 (2 * FA_ARR)           // Q hi+lo: 36864
#define FA_STAGE (2 * FA_ARR)         // K,V: 36864
#define FA_SMEM (FA_KV0 + 2 * FA_STAGE)  // 110592 (x2 CTAs = 221KB)

__global__ __launch_bounds__(256, 2)
void flash_mma_kernel(const __half* __restrict__ qh,
                      const __half* __restrict__ ql,
                      __half* __restrict__ oh)
{
    extern __shared__ __half fsm[];
    const uint32_t sb = smem_u32(fsm);

    const int tid  = threadIdx.x;
    const int lane = tid & 31;
    const int wq   = tid >> 5;
    const int qt   = (int)gridDim.x - 1 - (int)blockIdx.x;   // big tiles first
    const int bh   = blockIdx.y;
    const int b    = bh / H_;
    const int h    = bh - b * H_;
    const int q0   = qt * 128;
    const long rowbase = (long)b * S_ * QKV_N + h * HD;

    const __half* kvsrc[2] = {qh + D_, qh + 2 * D_};   // K hi, V hi

    // prologue: Q hi/lo
    {
        const __half* qsrc[2] = {qh, ql};
#pragma unroll
        for (int t = 0; t < 2; ++t) {
#pragma unroll
            for (int it = 0; it < 4; ++it) {
                int chunk = tid + it * 256;
                int r = chunk >> 3, c = chunk & 7;
                uint32_t dst = sb + t * FA_ARR + (r * FA_LD + c * 8) * 2;
                CP_ASYNC16(dst, (const void*)&qsrc[t][rowbase + (long)(q0 + r) * QKV_N + c * 8]);
            }
        }
    }
    auto kv_issue = [&](int kt, int stage) {
        const int k0 = kt * 128;
        const uint32_t sdst = sb + FA_KV0 + stage * FA_STAGE;
#pragma unroll
        for (int t = 0; t < 2; ++t) {
#pragma unroll
            for (int it = 0; it < 4; ++it) {
                int chunk = tid + it * 256;
                int r = chunk >> 3, c = chunk & 7;
                uint32_t dst = sdst + t * FA_ARR + (r * FA_LD + c * 8) * 2;
                CP_ASYNC16(dst, (const void*)&kvsrc[t][rowbase + (long)(k0 + r) * QKV_N + c * 8]);
            }
        }
    };
    kv_issue(0, 0);
    CP_COMMIT();
    CP_WAIT0();
    __syncthreads();

    float o[8][4];
#pragma unroll
    for (int j = 0; j < 8; ++j)
#pragma unroll
        for (int r = 0; r < 4; ++r) o[j][r] = 0.f;
    float rm[2] = {-1e30f, -1e30f};
    float rl[2] = {0.f, 0.f};

    const int r0 = lane >> 2;
    const int c0 = (lane & 3) * 2;
    const int arow = wq * 16 + (lane & 15);
    const int acol = (lane >> 4) * 8;
    const int krow = (lane & 15);
    const int kcol = (lane >> 4) * 8;
    const int vr = (lane & 7) + ((lane >> 3) & 1) * 8;
    const int vc = (lane >> 4) * 8;

    for (int kt = 0; kt <= qt; ++kt) {
        if (kt < qt) { kv_issue(kt + 1, (kt + 1) & 1); CP_COMMIT(); }

        const uint32_t ukv = sb + FA_KV0 + (kt & 1) * FA_STAGE;
        const uint32_t uKh = ukv, uVh = ukv + FA_ARR;

        // S = Q K^T over 128 keys (Q 2-term, K 1-term)
        float sc[16][4];
#pragma unroll
        for (int j = 0; j < 16; ++j)
#pragma unroll
            for (int r = 0; r < 4; ++r) sc[j][r] = 0.f;

#pragma unroll
        for (int ks = 0; ks < 4; ++ks) {
            uint32_t qfh[4], qfl[4];
            uint32_t qoff = (arow * FA_LD + ks * 16 + acol) * 2;
            LDM_X4(qfh, sb + qoff);
            LDM_X4(qfl, sb + FA_ARR + qoff);
#pragma unroll
            for (int j2 = 0; j2 < 8; ++j2) {
                uint32_t off = ((j2 * 16 + krow) * FA_LD + ks * 16 + kcol) * 2;
                uint32_t kh[4];
                LDM_X4(kh, uKh + off);
                MMA_F16R(sc[2*j2],   qfh, kh[0], kh[2]);
                MMA_F16R(sc[2*j2+1], qfh, kh[1], kh[3]);
                MMA_F16R(sc[2*j2],   qfl, kh[0], kh[2]);
                MMA_F16R(sc[2*j2+1], qfl, kh[1], kh[3]);
            }
        }

        // causal mask (diagonal tile)
        if (kt == qt) {
            int row0 = wq * 16 + r0;
            int row1 = row0 + 8;
#pragma unroll
            for (int j = 0; j < 16; ++j) {
                int col = j * 8 + c0;
                if (col     > row0) sc[j][0] = -1e30f;
                if (col + 1 > row0) sc[j][1] = -1e30f;
                if (col     > row1) sc[j][2] = -1e30f;
                if (col + 1 > row1) sc[j][3] = -1e30f;
            }
        }

        // online softmax (log2 domain; scores pre-scaled by log2e)
        float mx0 = -1e30f, mx1 = -1e30f;
#pragma unroll
        for (int j = 0; j < 16; ++j) {
            mx0 = fmaxf(mx0, fmaxf(sc[j][0], sc[j][1]));
            mx1 = fmaxf(mx1, fmaxf(sc[j][2], sc[j][3]));
        }
        mx0 = fmaxf(mx0, __shfl_xor_sync(0xffffffffu, mx0, 1));
        mx0 = fmaxf(mx0, __shfl_xor_sync(0xffffffffu, mx0, 2));
        mx1 = fmaxf(mx1, __shfl_xor_sync(0xffffffffu, mx1, 1));
        mx1 = fmaxf(mx1, __shfl_xor_sync(0xffffffffu, mx1, 2));

        float mn0 = fmaxf(rm[0], mx0);
        float mn1 = fmaxf(rm[1], mx1);
        float a0 = ex2f(rm[0] - mn0);
        float a1 = ex2f(rm[1] - mn1);
        rm[0] = mn0; rm[1] = mn1;

        float s0 = 0.f, s1 = 0.f;
#pragma unroll
        for (int j = 0; j < 16; ++j) {
            sc[j][0] = ex2f(sc[j][0] - mn0); s0 += sc[j][0];
            sc[j][1] = ex2f(sc[j][1] - mn0); s0 += sc[j][1];
            sc[j][2] = ex2f(sc[j][2] - mn1); s1 += sc[j][2];
            sc[j][3] = ex2f(sc[j][3] - mn1); s1 += sc[j][3];
        }
        s0 += __shfl_xor_sync(0xffffffffu, s0, 1);
        s0 += __shfl_xor_sync(0xffffffffu, s0, 2);
        s1 += __shfl_xor_sync(0xffffffffu, s1, 1);
        s1 += __shfl_xor_sync(0xffffffffu, s1, 2);
        rl[0] = rl[0] * a0 + s0;
        rl[1] = rl[1] * a1 + s1;
#pragma unroll
        for (int j = 0; j < 8; ++j) {
            o[j][0] *= a0; o[j][1] *= a0;
            o[j][2] *= a1; o[j][3] *= a1;
        }

        // O += P V  (P single fp16, V single fp16)
#pragma unroll
        for (int ks2 = 0; ks2 < 8; ++ks2) {
            uint32_t pf[4];
            pf[0] = pack_h2(sc[2*ks2][0],   sc[2*ks2][1]);
            pf[1] = pack_h2(sc[2*ks2][2],   sc[2*ks2][3]);
            pf[2] = pack_h2(sc[2*ks2+1][0], sc[2*ks2+1][1]);
            pf[3] = pack_h2(sc[2*ks2+1][2], sc[2*ks2+1][3]);
#pragma unroll
            for (int jp = 0; jp < 4; ++jp) {
                uint32_t voff = ((ks2 * 16 + vr) * FA_LD + jp * 16 + vc) * 2;
                uint32_t vh[4];
                LDM_X4T(vh, uVh + voff);
                MMA_F16R(o[2*jp],   pf, vh[0], vh[1]);
                MMA_F16R(o[2*jp+1], pf, vh[2], vh[3]);
            }
        }

        if (kt < qt) { CP_WAIT0(); __syncthreads(); }
    }

    // epilogue: normalize, store hi-only fp16
    float inv0 = 1.f / rl[0];
    float inv1 = 1.f / rl[1];
    long grow0 = (long)b * S_ + q0 + wq * 16 + r0;
#pragma unroll
    for (int j = 0; j < 8; ++j) {
        int col = h * HD + j * 8 + c0;
        *(__half2*)&oh[grow0 * D_ + col] = __half2(
            __float2half_rn(o[j][0] * inv0), __float2half_rn(o[j][1] * inv0));
        *(__half2*)&oh[(grow0 + 8) * D_ + col] = __half2(
            __float2half_rn(o[j][2] * inv1), __float2half_rn(o[j][3] * inv1));
    }
}

// ---------------------------------------------------------------------------
extern "C" void kernel_launch(void* const* d_in, const int* in_sizes, int n_in,
                              void* d_out, int out_size)
{
    const float* x    = (const float*)d_in[0];
    const float* Wqkv = (const float*)d_in[1];
    const float* bqkv = (const float*)d_in[2];
    const float* Wp   = (const float*)d_in[3];
    const float* bp   = (const float*)d_in[4];
    float* out = (float*)d_out;

    __half *qh, *ql, *ah, *al, *bhp;
    cudaGetSymbolAddress((void**)&qh, g_qh);
    cudaGetSymbolAddress((void**)&ql, g_ql);
    cudaGetSymbolAddress((void**)&ah, g_ah);
    cudaGetSymbolAddress((void**)&al, g_al);
    cudaGetSymbolAddress((void**)&bhp, g_bh);

    cudaFuncSetAttribute(gemm_mma_kernel<1>,
                         cudaFuncAttributeMaxDynamicSharedMemorySize, G_SMEM);
    cudaFuncSetAttribute(gemm_mma_kernel<0>,
                         cudaFuncAttributeMaxDynamicSharedMemorySize, G_SMEM);
    cudaFuncSetAttribute(flash_mma_kernel,
                         cudaFuncAttributeMaxDynamicSharedMemorySize, FA_SMEM);

    const int n4 = M_ * D_ / 4;
    const float qscale = 0.125f * 1.44269504088896340736f;   // 1/sqrt(hd) * log2(e)

    // 1) split x; convert Wqkv; QKV GEMM (A 2-term only for Q cols)
    split_kernel<<<(n4 + 255) / 256, 256>>>(x, ah, al, n4);
    transpose_cvt_kernel<<<dim3(QKV_N / 32, D_ / 32), dim3(32, 8)>>>(Wqkv, bhp, D_, QKV_N);
    gemm_mma_kernel<1><<<dim3(QKV_N / 128, M_ / 128), 256, G_SMEM>>>(
        ah, al, bhp, bqkv, nullptr, qh, ql, M_, QKV_N, D_, D_, qscale, D_, D_);

    // 2) flash attention (fp16 in, hi-only fp16 out)
    flash_mma_kernel<<<dim3(S_ / 128, B_ * H_), 256, FA_SMEM>>>(qh, ql, ah);

    // 3) convert Wp; proj GEMM (A 1-term) -> fp32 out
    transpose_cvt_kernel<<<dim3(D_ / 32, D_ / 32), dim3(32, 8)>>>(Wp, bhp, D_, D_);
    gemm_mma_kernel<0><<<dim3(D_ / 128, M_ / 128), 256, G_SMEM>>>(
        ah, ah, bhp, bp, out, nullptr, nullptr, M_, D_, D_, 0, 1.f, 0, 0);
}

// round 16
// speedup vs baseline: 1.6915x; 1.0041x over previous
#include <cuda_runtime.h>
#include <cuda_fp16.h>
#include <cstdint>
#include <math.h>

#define B_    4
#define S_    2048
#define D_    768
#define H_    12
#define HD    64
#define QKV_N (3*D_)      // 2304
#define M_    (B_*S_)     // 8192

// Scratch (no cudaMalloc allowed)
__device__ __half g_qh[M_ * QKV_N];   // qkv hi fp16 (Q pre-scaled by 0.125*log2e)
__device__ __half g_ql[M_ * QKV_N];   // qkv lo fp16 (only Q region valid)
__device__ __half g_ah[M_ * D_];
__device__ __half g_al[M_ * D_];
__device__ __half g_bh[QKV_N * D_];   // weights single fp16 [N,K]

// ---------------------------------------------------------------------------
__device__ __forceinline__ uint32_t smem_u32(const void* p) {
    uint32_t a;
    asm("{ .reg .u64 t; cvta.to.shared.u64 t, %1; cvt.u32.u64 %0, t; }" : "=r"(a) : "l"(p));
    return a;
}

__device__ __forceinline__ float ex2f(float x) {
    float r;
    asm("ex2.approx.ftz.f32 %0, %1;" : "=f"(r) : "f"(x));
    return r;
}

__device__ __forceinline__ uint32_t ex2_h2(uint32_t d) {
    uint32_t r;
    asm("ex2.approx.f16x2 %0, %1;" : "=r"(r) : "r"(d));
    return r;
}

#define CP_ASYNC16(dst, src) \
    asm volatile("cp.async.cg.shared.global [%0], [%1], 16;" :: "r"(dst), "l"(src))
#define CP_COMMIT() asm volatile("cp.async.commit_group;" ::: "memory")
#define CP_WAIT0()  asm volatile("cp.async.wait_group 0;" ::: "memory")

#define LDM_X4(r, addr) \
    asm volatile("ldmatrix.sync.aligned.m8n8.x4.shared.b16 {%0,%1,%2,%3}, [%4];" \
        : "=r"((r)[0]), "=r"((r)[1]), "=r"((r)[2]), "=r"((r)[3]) : "r"(addr))
#define LDM_X4T(r, addr) \
    asm volatile("ldmatrix.sync.aligned.m8n8.x4.trans.shared.b16 {%0,%1,%2,%3}, [%4];" \
        : "=r"((r)[0]), "=r"((r)[1]), "=r"((r)[2]), "=r"((r)[3]) : "r"(addr))
#define LDM_X2(r, addr) \
    asm volatile("ldmatrix.sync.aligned.m8n8.x2.shared.b16 {%0,%1}, [%2];" \
        : "=r"((r)[0]), "=r"((r)[1]) : "r"(addr))
#define LDM_X2T(r, addr) \
    asm volatile("ldmatrix.sync.aligned.m8n8.x2.trans.shared.b16 {%0,%1}, [%2];" \
        : "=r"((r)[0]), "=r"((r)[1]) : "r"(addr))
#define MMA_F16(d, a, b) \
    asm volatile("mma.sync.aligned.m16n8k16.row.col.f32.f16.f16.f32 " \
        "{%0,%1,%2,%3}, {%4,%5,%6,%7}, {%8,%9}, {%0,%1,%2,%3};" \
        : "+f"((d)[0]), "+f"((d)[1]), "+f"((d)[2]), "+f"((d)[3]) \
        : "r"((a)[0]), "r"((a)[1]), "r"((a)[2]), "r"((a)[3]), \
          "r"((b)[0]), "r"((b)[1]))
#define MMA_F16R(d, a, b0r, b1r) \
    asm volatile("mma.sync.aligned.m16n8k16.row.col.f32.f16.f16.f32 " \
        "{%0,%1,%2,%3}, {%4,%5,%6,%7}, {%8,%9}, {%0,%1,%2,%3};" \
        : "+f"((d)[0]), "+f"((d)[1]), "+f"((d)[2]), "+f"((d)[3]) \
        : "r"((a)[0]), "r"((a)[1]), "r"((a)[2]), "r"((a)[3]), \
          "r"(b0r), "r"(b1r))

__device__ __forceinline__ uint32_t pack_h2(float lo, float hi) {
    uint32_t r;
    asm("cvt.rn.f16x2.f32 %0, %1, %2;" : "=r"(r) : "f"(hi), "f"(lo));
    return r;
}

__device__ __forceinline__ void store_split4h(__half* ph, __half* pl, float4 v) {
    __half h0 = __float2half_rn(v.x), h1 = __float2half_rn(v.y);
    __half h2 = __float2half_rn(v.z), h3 = __float2half_rn(v.w);
    *(__half2*)(ph)     = __half2(h0, h1);
    *(__half2*)(ph + 2) = __half2(h2, h3);
    *(__half2*)(pl)     = __half2(
        __float2half_rn(v.x - __half2float(h0)),
        __float2half_rn(v.y - __half2float(h1)));
    *(__half2*)(pl + 2) = __half2(
        __float2half_rn(v.z - __half2float(h2)),
        __float2half_rn(v.w - __half2float(h3)));
}

// ---------------------------------------------------------------------------
__global__ void split_kernel(const float* __restrict__ in,
                             __half* __restrict__ hi,
                             __half* __restrict__ lo, int n4)
{
    int i = blockIdx.x * blockDim.x + threadIdx.x;
    if (i >= n4) return;
    float4 v = ((const float4*)in)[i];
    store_split4h(hi + 4 * (long)i, lo + 4 * (long)i, v);
}

// W[K,N] fp32 -> Bh[N,K] fp16 single (transpose + convert)
__global__ void transpose_cvt_kernel(const float* __restrict__ W,
                                     __half* __restrict__ Bh,
                                     int K, int N)
{
    __shared__ float t[32][33];
    int n0 = blockIdx.x * 32, k0 = blockIdx.y * 32;
    int tx = threadIdx.x, ty = threadIdx.y;
#pragma unroll
    for (int j = 0; j < 4; ++j)
        t[ty + j*8][tx] = W[(long)(k0 + ty + j*8) * N + n0 + tx];
    __syncthreads();
#pragma unroll
    for (int j = 0; j < 4; ++j)
        Bh[(long)(n0 + ty + j*8) * K + k0 + tx] = __float2half_rn(t[tx][ty + j*8]);
}

// ---------------------------------------------------------------------------
// fp16 GEMM: C = A[M,K] @ Bh[N,K]^T + bias.
// A is 2-term (Ah+Al) for output-column blocks with n0 < a_lo_ncols.
// ---------------------------------------------------------------------------
#define LDA 40
#define G_ARR (128 * LDA * 2)        // 10240
#define G_STAGE (3 * G_ARR)          // 30720
#define G_SMEM (2 * G_STAGE)         // 61440

template<int SPLIT_OUT>
__global__ __launch_bounds__(256, 2)
void gemm_mma_kernel(const __half* __restrict__ Ah,
                     const __half* __restrict__ Al,
                     const __half* __restrict__ Bh,
                     const float* __restrict__ bias,
                     float* __restrict__ C,
                     __half* __restrict__ Ch,
                     __half* __restrict__ Cl,
                     int M, int N, int K, int scale_cols, float scale,
                     int lo_cols, int a_lo_ncols)
{
    extern __shared__ __half gsm[];
    const uint32_t sb = smem_u32(gsm);

    const int tid  = threadIdx.x;
    const int lane = tid & 31;
    const int wid  = tid >> 5;
    const int wm   = wid >> 2;
    const int wn   = wid & 3;
    const int m0   = blockIdx.y * 128;
    const int n0   = blockIdx.x * 128;
    const int KT   = K / 32;
    const bool two = (n0 < a_lo_ncols);   // uniform per CTA

    float acc[4][4][4];
#pragma unroll
    for (int i = 0; i < 4; ++i)
#pragma unroll
        for (int j = 0; j < 4; ++j)
#pragma unroll
            for (int r = 0; r < 4; ++r) acc[i][j][r] = 0.f;

    const int a_row = lane & 15;
    const int a_kb  = (lane >> 4) * 8;
    const int b_row = lane & 7;
    const int b_kb  = ((lane >> 3) & 1) * 8;

    auto cp_issue = [&](int kt, int stage) {
        const int k0 = kt * 32;
        const uint32_t sdst = sb + stage * G_STAGE;
#pragma unroll
        for (int it = 0; it < 2; ++it) {
            int chunk = tid + it * 256;
            int r = chunk >> 2, c = chunk & 3;
            uint32_t soff = (r * LDA + c * 8) * 2;
            CP_ASYNC16(sdst + soff, (const void*)&Ah[(long)(m0 + r) * K + k0 + c * 8]);
            if (two)
                CP_ASYNC16(sdst + G_ARR + soff, (const void*)&Al[(long)(m0 + r) * K + k0 + c * 8]);
            CP_ASYNC16(sdst + 2 * G_ARR + soff, (const void*)&Bh[(long)(n0 + r) * K + k0 + c * 8]);
        }
    };

    cp_issue(0, 0);
    CP_COMMIT();

    for (int kt = 0; kt < KT; ++kt) {
        CP_WAIT0();
        __syncthreads();
        if (kt + 1 < KT) { cp_issue(kt + 1, (kt + 1) & 1); CP_COMMIT(); }

        const uint32_t ub  = sb + (kt & 1) * G_STAGE;
        const uint32_t uAh = ub, uAl = ub + G_ARR, uBh = ub + 2 * G_ARR;

#pragma unroll
        for (int ks = 0; ks < 2; ++ks) {
            const int kc = ks * 16;
            uint32_t bh[4][2];
#pragma unroll
            for (int j = 0; j < 4; ++j) {
                uint32_t off = ((wn * 32 + j * 8 + b_row) * LDA + kc + b_kb) * 2;
                LDM_X2(bh[j], uBh + off);
            }
#pragma unroll
            for (int i = 0; i < 4; ++i) {
                uint32_t off = ((wm * 64 + i * 16 + a_row) * LDA + kc + a_kb) * 2;
                uint32_t ah[4];
                LDM_X4(ah, uAh + off);
#pragma unroll
                for (int j = 0; j < 4; ++j)
                    MMA_F16(acc[i][j], ah, bh[j]);
                if (two) {
                    uint32_t al[4];
                    LDM_X4(al, uAl + off);
#pragma unroll
                    for (int j = 0; j < 4; ++j)
                        MMA_F16(acc[i][j], al, bh[j]);
                }
            }
        }
        __syncthreads();
    }

    const int qr = lane >> 2;
    const int qc = (lane & 3) * 2;
#pragma unroll
    for (int i = 0; i < 4; ++i) {
#pragma unroll
        for (int j = 0; j < 4; ++j) {
            int col = n0 + wn * 32 + j * 8 + qc;
            float b0 = __ldg(&bias[col]);
            float b1 = __ldg(&bias[col + 1]);
            long r0 = m0 + wm * 64 + i * 16 + qr;
            float v00 = acc[i][j][0] + b0, v01 = acc[i][j][1] + b1;
            float v10 = acc[i][j][2] + b0, v11 = acc[i][j][3] + b1;
            if (SPLIT_OUT) {
                float s = (col < scale_cols) ? scale : 1.f;
                v00 *= s; v01 *= s; v10 *= s; v11 *= s;
                __half h00 = __float2half_rn(v00), h01 = __float2half_rn(v01);
                __half h10 = __float2half_rn(v10), h11 = __float2half_rn(v11);
                *(__half2*)&Ch[r0 * N + col]       = __half2(h00, h01);
                *(__half2*)&Ch[(r0 + 8) * N + col] = __half2(h10, h11);
                if (col < lo_cols) {
                    *(__half2*)&Cl[r0 * N + col] = __half2(
                        __float2half_rn(v00 - __half2float(h00)),
                        __float2half_rn(v01 - __half2float(h01)));
                    *(__half2*)&Cl[(r0 + 8) * N + col] = __half2(
                        __float2half_rn(v10 - __half2float(h10)),
                        __float2half_rn(v11 - __half2float(h11)));
                }
            } else {
                *(float2*)&C[r0 * N + col]       = make_float2(v00, v01);
                *(float2*)&C[(r0 + 8) * N + col] = make_float2(v10, v11);
            }
        }
    }
}

// ---------------------------------------------------------------------------
// Flash attention fp16: Q 2-term x K 1-term; P 1-term x V 1-term.
// f16x2 MUFU softmax; l computed by ones-column PV MMA (V smem padding col 64
// = 1.0, cols 65-71 = 0). 128-key tiles, cp.async double-buffered, 2 CTAs/SM.
// ---------------------------------------------------------------------------
#define FA_LD 72
#define FA_ARR (128 * FA_LD * 2)      // 18432
#define FA_KV0 (2 * FA_ARR)           // Q hi+lo: 36864
#define FA_STAGE (2 * FA_ARR)         // K,V: 36864
#define FA_SMEM (FA_KV0 + 2 * FA_STAGE)  // 110592 (x2 CTAs = 221KB)

__global__ __launch_bounds__(256, 2)
void flash_mma_kernel(const __half* __restrict__ qh,
                      const __half* __restrict__ ql,
                      __half* __restrict__ oh)
{
    extern __shared__ __half fsm[];
    const uint32_t sb = smem_u32(fsm);

    const int tid  = threadIdx.x;
    const int lane = tid & 31;
    const int wq   = tid >> 5;
    const int qt   = (int)gridDim.x - 1 - (int)blockIdx.x;   // big tiles first
    const int bh   = blockIdx.y;
    const int b    = bh / H_;
    const int h    = bh - b * H_;
    const int q0   = qt * 128;
    const long rowbase = (long)b * S_ * QKV_N + h * HD;

    const __half* kvsrc[2] = {qh + D_, qh + 2 * D_};   // K hi, V hi

    // init V padding cols 64-71 = {1,0,...,0} for both stages (ones-column l)
    if (tid < 256) {
        int stage = tid >> 7, r = tid & 127;
        __half* vpad = fsm + (FA_KV0 + stage * FA_STAGE + FA_ARR) / 2 + r * FA_LD + 64;
        *(__half2*)(vpad)     = __half2(__float2half(1.f), __float2half(0.f));
        *(__half2*)(vpad + 2) = __half2(__float2half(0.f), __float2half(0.f));
        *(__half2*)(vpad + 4) = __half2(__float2half(0.f), __float2half(0.f));
        *(__half2*)(vpad + 6) = __half2(__float2half(0.f), __float2half(0.f));
    }

    // prologue: Q hi/lo
    {
        const __half* qsrc[2] = {qh, ql};
#pragma unroll
        for (int t = 0; t < 2; ++t) {
#pragma unroll
            for (int it = 0; it < 4; ++it) {
                int chunk = tid + it * 256;
                int r = chunk >> 3, c = chunk & 7;
                uint32_t dst = sb + t * FA_ARR + (r * FA_LD + c * 8) * 2;
                CP_ASYNC16(dst, (const void*)&qsrc[t][rowbase + (long)(q0 + r) * QKV_N + c * 8]);
            }
        }
    }
    auto kv_issue = [&](int kt, int stage) {
        const int k0 = kt * 128;
        const uint32_t sdst = sb + FA_KV0 + stage * FA_STAGE;
#pragma unroll
        for (int t = 0; t < 2; ++t) {
#pragma unroll
            for (int it = 0; it < 4; ++it) {
                int chunk = tid + it * 256;
                int r = chunk >> 3, c = chunk & 7;
                uint32_t dst = sdst + t * FA_ARR + (r * FA_LD + c * 8) * 2;
                CP_ASYNC16(dst, (const void*)&kvsrc[t][rowbase + (long)(k0 + r) * QKV_N + c * 8]);
            }
        }
    };
    kv_issue(0, 0);
    CP_COMMIT();
    CP_WAIT0();
    __syncthreads();

    float o[8][4];
#pragma unroll
    for (int j = 0; j < 8; ++j)
#pragma unroll
        for (int r = 0; r < 4; ++r) o[j][r] = 0.f;
    float ol[4] = {0.f, 0.f, 0.f, 0.f};       // ones-column accumulator (l)
    float rm[2] = {-1e30f, -1e30f};

    const int r0 = lane >> 2;
    const int c0 = (lane & 3) * 2;
    const int arow = wq * 16 + (lane & 15);
    const int acol = (lane >> 4) * 8;
    const int krow = (lane & 15);
    const int kcol = (lane >> 4) * 8;
    const int vr = (lane & 7) + ((lane >> 3) & 1) * 8;
    const int vc = (lane >> 4) * 8;
    const int v1r = lane & 15;

    for (int kt = 0; kt <= qt; ++kt) {
        if (kt < qt) { kv_issue(kt + 1, (kt + 1) & 1); CP_COMMIT(); }

        const uint32_t ukv = sb + FA_KV0 + (kt & 1) * FA_STAGE;
        const uint32_t uKh = ukv, uVh = ukv + FA_ARR;

        // S = Q K^T over 128 keys (Q 2-term, K 1-term)
        float sc[16][4];
#pragma unroll
        for (int j = 0; j < 16; ++j)
#pragma unroll
            for (int r = 0; r < 4; ++r) sc[j][r] = 0.f;

#pragma unroll
        for (int ks = 0; ks < 4; ++ks) {
            uint32_t qfh[4], qfl[4];
            uint32_t qoff = (arow * FA_LD + ks * 16 + acol) * 2;
            LDM_X4(qfh, sb + qoff);
            LDM_X4(qfl, sb + FA_ARR + qoff);
#pragma unroll
            for (int j2 = 0; j2 < 8; ++j2) {
                uint32_t off = ((j2 * 16 + krow) * FA_LD + ks * 16 + kcol) * 2;
                uint32_t kh[4];
                LDM_X4(kh, uKh + off);
                MMA_F16R(sc[2*j2],   qfh, kh[0], kh[2]);
                MMA_F16R(sc[2*j2+1], qfh, kh[1], kh[3]);
                MMA_F16R(sc[2*j2],   qfl, kh[0], kh[2]);
                MMA_F16R(sc[2*j2+1], qfl, kh[1], kh[3]);
            }
        }

        // causal mask (diagonal tile)
        if (kt == qt) {
            int row0 = wq * 16 + r0;
            int row1 = row0 + 8;
#pragma unroll
            for (int j = 0; j < 16; ++j) {
                int col = j * 8 + c0;
                if (col     > row0) sc[j][0] = -1e30f;
                if (col + 1 > row0) sc[j][1] = -1e30f;
                if (col     > row1) sc[j][2] = -1e30f;
                if (col + 1 > row1) sc[j][3] = -1e30f;
            }
        }

        // online softmax max (fp32)
        float mx0 = -1e30f, mx1 = -1e30f;
#pragma unroll
        for (int j = 0; j < 16; ++j) {
            mx0 = fmaxf(mx0, fmaxf(sc[j][0], sc[j][1]));
            mx1 = fmaxf(mx1, fmaxf(sc[j][2], sc[j][3]));
        }
        mx0 = fmaxf(mx0, __shfl_xor_sync(0xffffffffu, mx0, 1));
        mx0 = fmaxf(mx0, __shfl_xor_sync(0xffffffffu, mx0, 2));
        mx1 = fmaxf(mx1, __shfl_xor_sync(0xffffffffu, mx1, 1));
        mx1 = fmaxf(mx1, __shfl_xor_sync(0xffffffffu, mx1, 2));

        float mn0 = fmaxf(rm[0], mx0);
        float mn1 = fmaxf(rm[1], mx1);
        float a0 = ex2f(rm[0] - mn0);
        float a1 = ex2f(rm[1] - mn1);
        rm[0] = mn0; rm[1] = mn1;

        // p = 2^(s-m) in packed fp16 (f16x2 MUFU); no explicit row sum needed
        uint32_t pp[16][2];
#pragma unroll
        for (int j = 0; j < 16; ++j) {
            pp[j][0] = ex2_h2(pack_h2(sc[j][0] - mn0, sc[j][1] - mn0));
            pp[j][1] = ex2_h2(pack_h2(sc[j][2] - mn1, sc[j][3] - mn1));
        }

        // rescale O and l-fragment
#pragma unroll
        for (int j = 0; j < 8; ++j) {
            o[j][0] *= a0; o[j][1] *= a0;
            o[j][2] *= a1; o[j][3] *= a1;
        }
        ol[0] *= a0; ol[1] *= a0;
        ol[2] *= a1; ol[3] *= a1;

        // O += P V (+ ones-column MMA accumulates row sums into ol)
#pragma unroll
        for (int ks2 = 0; ks2 < 8; ++ks2) {
            uint32_t pf[4] = {pp[2*ks2][0], pp[2*ks2][1], pp[2*ks2+1][0], pp[2*ks2+1][1]};
#pragma unroll
            for (int jp = 0; jp < 4; ++jp) {
                uint32_t voff = ((ks2 * 16 + vr) * FA_LD + jp * 16 + vc) * 2;
                uint32_t vh[4];
                LDM_X4T(vh, uVh + voff);
                MMA_F16R(o[2*jp],   pf, vh[0], vh[1]);
                MMA_F16R(o[2*jp+1], pf, vh[2], vh[3]);
            }
            uint32_t v1[2];
            uint32_t voff1 = ((ks2 * 16 + v1r) * FA_LD + 64) * 2;
            LDM_X2T(v1, uVh + voff1);
            MMA_F16R(ol, pf, v1[0], v1[1]);
        }

        if (kt < qt) { CP_WAIT0(); __syncthreads(); }
    }

    // epilogue: l lives in quad-leader's ol[0]/ol[2]; broadcast, normalize, store
    float l0 = __shfl_sync(0xffffffffu, ol[0], lane & ~3);
    float l1 = __shfl_sync(0xffffffffu, ol[2], lane & ~3);
    float inv0 = 1.f / l0;
    float inv1 = 1.f / l1;
    long grow0 = (long)b * S_ + q0 + wq * 16 + r0;
#pragma unroll
    for (int j = 0; j < 8; ++j) {
        int col = h * HD + j * 8 + c0;
        *(__half2*)&oh[grow0 * D_ + col] = __half2(
            __float2half_rn(o[j][0] * inv0), __float2half_rn(o[j][1] * inv0));
        *(__half2*)&oh[(grow0 + 8) * D_ + col] = __half2(
            __float2half_rn(o[j][2] * inv1), __float2half_rn(o[j][3] * inv1));
    }
}

// ---------------------------------------------------------------------------
extern "C" void kernel_launch(void* const* d_in, const int* in_sizes, int n_in,
                              void* d_out, int out_size)
{
    const float* x    = (const float*)d_in[0];
    const float* Wqkv = (const float*)d_in[1];
    const float* bqkv = (const float*)d_in[2];
    const float* Wp   = (const float*)d_in[3];
    const float* bp   = (const float*)d_in[4];
    float* out = (float*)d_out;

    __half *qh, *ql, *ah, *al, *bhp;
    cudaGetSymbolAddress((void**)&qh, g_qh);
    cudaGetSymbolAddress((void**)&ql, g_ql);
    cudaGetSymbolAddress((void**)&ah, g_ah);
    cudaGetSymbolAddress((void**)&al, g_al);
    cudaGetSymbolAddress((void**)&bhp, g_bh);

    cudaFuncSetAttribute(gemm_mma_kernel<1>,
                         cudaFuncAttributeMaxDynamicSharedMemorySize, G_SMEM);
    cudaFuncSetAttribute(gemm_mma_kernel<0>,
                         cudaFuncAttributeMaxDynamicSharedMemorySize, G_SMEM);
    cudaFuncSetAttribute(flash_mma_kernel,
                         cudaFuncAttributeMaxDynamicSharedMemorySize, FA_SMEM);

    const int n4 = M_ * D_ / 4;
    const float qscale = 0.125f * 1.44269504088896340736f;   // 1/sqrt(hd) * log2(e)

    // 1) split x; convert Wqkv; QKV GEMM (A 2-term only for Q cols)
    split_kernel<<<(n4 + 255) / 256, 256>>>(x, ah, al, n4);
    transpose_cvt_kernel<<<dim3(QKV_N / 32, D_ / 32), dim3(32, 8)>>>(Wqkv, bhp, D_, QKV_N);
    gemm_mma_kernel<1><<<dim3(QKV_N / 128, M_ / 128), 256, G_SMEM>>>(
        ah, al, bhp, bqkv, nullptr, qh, ql, M_, QKV_N, D_, D_, qscale, D_, D_);

    // 2) flash attention (fp16 in, hi-only fp16 out)
    flash_mma_kernel<<<dim3(S_ / 128, B_ * H_), 256, FA_SMEM>>>(qh, ql, ah);

    // 3) convert Wp; proj GEMM (A 1-term) -> fp32 out
    transpose_cvt_kernel<<<dim3(D_ / 32, D_ / 32), dim3(32, 8)>>>(Wp, bhp, D_, D_);
    gemm_mma_kernel<0><<<dim3(D_ / 128, M_ / 128), 256, G_SMEM>>>(
        ah, ah, bhp, bp, out, nullptr, nullptr, M_, D_, D_, 0, 1.f, 0, 0);
}

// round 17
// speedup vs baseline: 2.3385x; 1.3825x over previous
#include <cuda_runtime.h>
#include <cuda_fp16.h>
#include <cstdint>
#include <math.h>

#define B_    4
#define S_    2048
#define D_    768
#define H_    12
#define HD    64
#define QKV_N (3*D_)      // 2304
#define M_    (B_*S_)     // 8192

// Scratch (no cudaMalloc allowed)
__device__ __half g_qh[M_ * QKV_N];   // qkv fp16 (Q pre-scaled by 0.125*log2e)
__device__ __half g_ah[M_ * D_];      // x fp16 / attention output fp16
__device__ __half g_bh[QKV_N * D_];   // weights fp16 [N,K]

// ---------------------------------------------------------------------------
__device__ __forceinline__ uint32_t smem_u32(const void* p) {
    uint32_t a;
    asm("{ .reg .u64 t; cvta.to.shared.u64 t, %1; cvt.u32.u64 %0, t; }" : "=r"(a) : "l"(p));
    return a;
}

__device__ __forceinline__ float ex2f(float x) {
    float r;
    asm("ex2.approx.ftz.f32 %0, %1;" : "=f"(r) : "f"(x));
    return r;
}

__device__ __forceinline__ uint32_t ex2_h2(uint32_t d) {
    uint32_t r;
    asm("ex2.approx.f16x2 %0, %1;" : "=r"(r) : "r"(d));
    return r;
}

#define CP_ASYNC16(dst, src) \
    asm volatile("cp.async.cg.shared.global [%0], [%1], 16;" :: "r"(dst), "l"(src))
#define CP_COMMIT() asm volatile("cp.async.commit_group;" ::: "memory")
#define CP_WAIT0()  asm volatile("cp.async.wait_group 0;" ::: "memory")

#define LDM_X4(r, addr) \
    asm volatile("ldmatrix.sync.aligned.m8n8.x4.shared.b16 {%0,%1,%2,%3}, [%4];" \
        : "=r"((r)[0]), "=r"((r)[1]), "=r"((r)[2]), "=r"((r)[3]) : "r"(addr))
#define LDM_X4T(r, addr) \
    asm volatile("ldmatrix.sync.aligned.m8n8.x4.trans.shared.b16 {%0,%1,%2,%3}, [%4];" \
        : "=r"((r)[0]), "=r"((r)[1]), "=r"((r)[2]), "=r"((r)[3]) : "r"(addr))
#define LDM_X2(r, addr) \
    asm volatile("ldmatrix.sync.aligned.m8n8.x2.shared.b16 {%0,%1}, [%2];" \
        : "=r"((r)[0]), "=r"((r)[1]) : "r"(addr))
#define LDM_X2T(r, addr) \
    asm volatile("ldmatrix.sync.aligned.m8n8.x2.trans.shared.b16 {%0,%1}, [%2];" \
        : "=r"((r)[0]), "=r"((r)[1]) : "r"(addr))
#define MMA_F16(d, a, b) \
    asm volatile("mma.sync.aligned.m16n8k16.row.col.f32.f16.f16.f32 " \
        "{%0,%1,%2,%3}, {%4,%5,%6,%7}, {%8,%9}, {%0,%1,%2,%3};" \
        : "+f"((d)[0]), "+f"((d)[1]), "+f"((d)[2]), "+f"((d)[3]) \
        : "r"((a)[0]), "r"((a)[1]), "r"((a)[2]), "r"((a)[3]), \
          "r"((b)[0]), "r"((b)[1]))
#define MMA_F16R(d, a, b0r, b1r) \
    asm volatile("mma.sync.aligned.m16n8k16.row.col.f32.f16.f16.f32 " \
        "{%0,%1,%2,%3}, {%4,%5,%6,%7}, {%8,%9}, {%0,%1,%2,%3};" \
        : "+f"((d)[0]), "+f"((d)[1]), "+f"((d)[2]), "+f"((d)[3]) \
        : "r"((a)[0]), "r"((a)[1]), "r"((a)[2]), "r"((a)[3]), \
          "r"(b0r), "r"(b1r))

__device__ __forceinline__ uint32_t pack_h2(float lo, float hi) {
    uint32_t r;
    asm("cvt.rn.f16x2.f32 %0, %1, %2;" : "=r"(r) : "f"(hi), "f"(lo));
    return r;
}

// ---------------------------------------------------------------------------
// fp32 -> fp16 convert (elementwise)
__global__ void cvt_kernel(const float* __restrict__ in,
                           __half* __restrict__ out, int n4)
{
    int i = blockIdx.x * blockDim.x + threadIdx.x;
    if (i >= n4) return;
    float4 v = ((const float4*)in)[i];
    __half2* o = (__half2*)(out + 4 * (long)i);
    o[0] = __half2(__float2half_rn(v.x), __float2half_rn(v.y));
    o[1] = __half2(__float2half_rn(v.z), __float2half_rn(v.w));
}

// W[K,N] fp32 -> Bh[N,K] fp16 (transpose + convert)
__global__ void transpose_cvt_kernel(const float* __restrict__ W,
                                     __half* __restrict__ Bh,
                                     int K, int N)
{
    __shared__ float t[32][33];
    int n0 = blockIdx.x * 32, k0 = blockIdx.y * 32;
    int tx = threadIdx.x, ty = threadIdx.y;
#pragma unroll
    for (int j = 0; j < 4; ++j)
        t[ty + j*8][tx] = W[(long)(k0 + ty + j*8) * N + n0 + tx];
    __syncthreads();
#pragma unroll
    for (int j = 0; j < 4; ++j)
        Bh[(long)(n0 + ty + j*8) * K + k0 + tx] = __float2half_rn(t[tx][ty + j*8]);
}

// ---------------------------------------------------------------------------
// fp16 1-term GEMM: C = A[M,K] @ Bh[N,K]^T + bias.
// SPLIT_OUT=1: fp16 out, cols < scale_cols multiplied by scale. Else fp32 out.
// ---------------------------------------------------------------------------
#define LDA 40
#define G_ARR (128 * LDA * 2)        // 10240
#define G_STAGE (2 * G_ARR)          // 20480
#define G_SMEM (2 * G_STAGE)         // 40960

template<int SPLIT_OUT>
__global__ __launch_bounds__(256, 2)
void gemm_mma_kernel(const __half* __restrict__ Ah,
                     const __half* __restrict__ Bh,
                     const float* __restrict__ bias,
                     float* __restrict__ C,
                     __half* __restrict__ Ch,
                     int M, int N, int K, int scale_cols, float scale)
{
    extern __shared__ __half gsm[];
    const uint32_t sb = smem_u32(gsm);

    const int tid  = threadIdx.x;
    const int lane = tid & 31;
    const int wid  = tid >> 5;
    const int wm   = wid >> 2;
    const int wn   = wid & 3;
    const int m0   = blockIdx.y * 128;
    const int n0   = blockIdx.x * 128;
    const int KT   = K / 32;

    float acc[4][4][4];
#pragma unroll
    for (int i = 0; i < 4; ++i)
#pragma unroll
        for (int j = 0; j < 4; ++j)
#pragma unroll
            for (int r = 0; r < 4; ++r) acc[i][j][r] = 0.f;

    const int a_row = lane & 15;
    const int a_kb  = (lane >> 4) * 8;
    const int b_row = lane & 7;
    const int b_kb  = ((lane >> 3) & 1) * 8;

    auto cp_issue = [&](int kt, int stage) {
        const int k0 = kt * 32;
        const uint32_t sdst = sb + stage * G_STAGE;
#pragma unroll
        for (int it = 0; it < 2; ++it) {
            int chunk = tid + it * 256;
            int r = chunk >> 2, c = chunk & 3;
            uint32_t soff = (r * LDA + c * 8) * 2;
            CP_ASYNC16(sdst + soff, (const void*)&Ah[(long)(m0 + r) * K + k0 + c * 8]);
            CP_ASYNC16(sdst + G_ARR + soff, (const void*)&Bh[(long)(n0 + r) * K + k0 + c * 8]);
        }
    };

    cp_issue(0, 0);
    CP_COMMIT();

    for (int kt = 0; kt < KT; ++kt) {
        CP_WAIT0();
        __syncthreads();
        if (kt + 1 < KT) { cp_issue(kt + 1, (kt + 1) & 1); CP_COMMIT(); }

        const uint32_t ub  = sb + (kt & 1) * G_STAGE;
        const uint32_t uAh = ub, uBh = ub + G_ARR;

#pragma unroll
        for (int ks = 0; ks < 2; ++ks) {
            const int kc = ks * 16;
            uint32_t bh[4][2];
#pragma unroll
            for (int j = 0; j < 4; ++j) {
                uint32_t off = ((wn * 32 + j * 8 + b_row) * LDA + kc + b_kb) * 2;
                LDM_X2(bh[j], uBh + off);
            }
#pragma unroll
            for (int i = 0; i < 4; ++i) {
                uint32_t off = ((wm * 64 + i * 16 + a_row) * LDA + kc + a_kb) * 2;
                uint32_t ah[4];
                LDM_X4(ah, uAh + off);
#pragma unroll
                for (int j = 0; j < 4; ++j)
                    MMA_F16(acc[i][j], ah, bh[j]);
            }
        }
        __syncthreads();
    }

    const int qr = lane >> 2;
    const int qc = (lane & 3) * 2;
#pragma unroll
    for (int i = 0; i < 4; ++i) {
#pragma unroll
        for (int j = 0; j < 4; ++j) {
            int col = n0 + wn * 32 + j * 8 + qc;
            float b0 = __ldg(&bias[col]);
            float b1 = __ldg(&bias[col + 1]);
            long r0 = m0 + wm * 64 + i * 16 + qr;
            float v00 = acc[i][j][0] + b0, v01 = acc[i][j][1] + b1;
            float v10 = acc[i][j][2] + b0, v11 = acc[i][j][3] + b1;
            if (SPLIT_OUT) {
                float s = (col < scale_cols) ? scale : 1.f;
                v00 *= s; v01 *= s; v10 *= s; v11 *= s;
                *(__half2*)&Ch[r0 * N + col] =
                    __half2(__float2half_rn(v00), __float2half_rn(v01));
                *(__half2*)&Ch[(r0 + 8) * N + col] =
                    __half2(__float2half_rn(v10), __float2half_rn(v11));
            } else {
                *(float2*)&C[r0 * N + col]       = make_float2(v00, v01);
                *(float2*)&C[(r0 + 8) * N + col] = make_float2(v10, v11);
            }
        }
    }
}

// ---------------------------------------------------------------------------
// Flash attention fp16, all operands 1-term. f16x2 MUFU softmax; l via
// ones-column PV MMA. 128-key tiles, cp.async double-buffered, 2 CTAs/SM.
// ---------------------------------------------------------------------------
#define FA_LD 72
#define FA_ARR (128 * FA_LD * 2)      // 18432
#define FA_KV0 (FA_ARR)               // Q: 18432
#define FA_STAGE (2 * FA_ARR)         // K,V: 36864
#define FA_SMEM (FA_KV0 + 2 * FA_STAGE)  // 92160 (x2 CTAs = 184KB)

__global__ __launch_bounds__(256, 2)
void flash_mma_kernel(const __half* __restrict__ qkv,
                      __half* __restrict__ oh)
{
    extern __shared__ __half fsm[];
    const uint32_t sb = smem_u32(fsm);

    const int tid  = threadIdx.x;
    const int lane = tid & 31;
    const int wq   = tid >> 5;
    const int qt   = (int)gridDim.x - 1 - (int)blockIdx.x;   // big tiles first
    const int bh   = blockIdx.y;
    const int b    = bh / H_;
    const int h    = bh - b * H_;
    const int q0   = qt * 128;
    const long rowbase = (long)b * S_ * QKV_N + h * HD;

    const __half* kvsrc[2] = {qkv + D_, qkv + 2 * D_};   // K, V

    // init V padding cols 64-71 = {1,0,...,0} for both stages (ones-column l)
    {
        int stage = tid >> 7, r = tid & 127;
        __half* vpad = fsm + (FA_KV0 + stage * FA_STAGE + FA_ARR) / 2 + r * FA_LD + 64;
        *(__half2*)(vpad)     = __half2(__float2half(1.f), __float2half(0.f));
        *(__half2*)(vpad + 2) = __half2(__float2half(0.f), __float2half(0.f));
        *(__half2*)(vpad + 4) = __half2(__float2half(0.f), __float2half(0.f));
        *(__half2*)(vpad + 6) = __half2(__float2half(0.f), __float2half(0.f));
    }

    // prologue: Q
#pragma unroll
    for (int it = 0; it < 4; ++it) {
        int chunk = tid + it * 256;
        int r = chunk >> 3, c = chunk & 7;
        uint32_t dst = sb + (r * FA_LD + c * 8) * 2;
        CP_ASYNC16(dst, (const void*)&qkv[rowbase + (long)(q0 + r) * QKV_N + c * 8]);
    }
    auto kv_issue = [&](int kt, int stage) {
        const int k0 = kt * 128;
        const uint32_t sdst = sb + FA_KV0 + stage * FA_STAGE;
#pragma unroll
        for (int t = 0; t < 2; ++t) {
#pragma unroll
            for (int it = 0; it < 4; ++it) {
                int chunk = tid + it * 256;
                int r = chunk >> 3, c = chunk & 7;
                uint32_t dst = sdst + t * FA_ARR + (r * FA_LD + c * 8) * 2;
                CP_ASYNC16(dst, (const void*)&kvsrc[t][rowbase + (long)(k0 + r) * QKV_N + c * 8]);
            }
        }
    };
    kv_issue(0, 0);
    CP_COMMIT();
    CP_WAIT0();
    __syncthreads();

    float o[8][4];
#pragma unroll
    for (int j = 0; j < 8; ++j)
#pragma unroll
        for (int r = 0; r < 4; ++r) o[j][r] = 0.f;
    float ol[4] = {0.f, 0.f, 0.f, 0.f};       // ones-column accumulator (l)
    float rm[2] = {-1e30f, -1e30f};

    const int r0 = lane >> 2;
    const int c0 = (lane & 3) * 2;
    const int arow = wq * 16 + (lane & 15);
    const int acol = (lane >> 4) * 8;
    const int krow = (lane & 15);
    const int kcol = (lane >> 4) * 8;
    const int vr = (lane & 7) + ((lane >> 3) & 1) * 8;
    const int vc = (lane >> 4) * 8;
    const int v1r = lane & 15;

    // hoist Q fragments (1-term: 16 regs)
    uint32_t qf[4][4];
#pragma unroll
    for (int ks = 0; ks < 4; ++ks) {
        uint32_t qoff = (arow * FA_LD + ks * 16 + acol) * 2;
        LDM_X4(qf[ks], sb + qoff);
    }

    for (int kt = 0; kt <= qt; ++kt) {
        if (kt < qt) { kv_issue(kt + 1, (kt + 1) & 1); CP_COMMIT(); }

        const uint32_t ukv = sb + FA_KV0 + (kt & 1) * FA_STAGE;
        const uint32_t uKh = ukv, uVh = ukv + FA_ARR;

        // S = Q K^T over 128 keys (1-term x 1-term)
        float sc[16][4];
#pragma unroll
        for (int j = 0; j < 16; ++j)
#pragma unroll
            for (int r = 0; r < 4; ++r) sc[j][r] = 0.f;

#pragma unroll
        for (int ks = 0; ks < 4; ++ks) {
#pragma unroll
            for (int j2 = 0; j2 < 8; ++j2) {
                uint32_t off = ((j2 * 16 + krow) * FA_LD + ks * 16 + kcol) * 2;
                uint32_t kh[4];
                LDM_X4(kh, uKh + off);
                MMA_F16R(sc[2*j2],   qf[ks], kh[0], kh[2]);
                MMA_F16R(sc[2*j2+1], qf[ks], kh[1], kh[3]);
            }
        }

        // causal mask (diagonal tile)
        if (kt == qt) {
            int row0 = wq * 16 + r0;
            int row1 = row0 + 8;
#pragma unroll
            for (int j = 0; j < 16; ++j) {
                int col = j * 8 + c0;
                if (col     > row0) sc[j][0] = -1e30f;
                if (col + 1 > row0) sc[j][1] = -1e30f;
                if (col     > row1) sc[j][2] = -1e30f;
                if (col + 1 > row1) sc[j][3] = -1e30f;
            }
        }

        // online softmax max (fp32)
        float mx0 = -1e30f, mx1 = -1e30f;
#pragma unroll
        for (int j = 0; j < 16; ++j) {
            mx0 = fmaxf(mx0, fmaxf(sc[j][0], sc[j][1]));
            mx1 = fmaxf(mx1, fmaxf(sc[j][2], sc[j][3]));
        }
        mx0 = fmaxf(mx0, __shfl_xor_sync(0xffffffffu, mx0, 1));
        mx0 = fmaxf(mx0, __shfl_xor_sync(0xffffffffu, mx0, 2));
        mx1 = fmaxf(mx1, __shfl_xor_sync(0xffffffffu, mx1, 1));
        mx1 = fmaxf(mx1, __shfl_xor_sync(0xffffffffu, mx1, 2));

        float mn0 = fmaxf(rm[0], mx0);
        float mn1 = fmaxf(rm[1], mx1);
        float a0 = ex2f(rm[0] - mn0);
        float a1 = ex2f(rm[1] - mn1);
        rm[0] = mn0; rm[1] = mn1;

        // p = 2^(s-m) in packed fp16 (f16x2 MUFU)
        uint32_t pp[16][2];
#pragma unroll
        for (int j = 0; j < 16; ++j) {
            pp[j][0] = ex2_h2(pack_h2(sc[j][0] - mn0, sc[j][1] - mn0));
            pp[j][1] = ex2_h2(pack_h2(sc[j][2] - mn1, sc[j][3] - mn1));
        }

        // rescale O and l-fragment
#pragma unroll
        for (int j = 0; j < 8; ++j) {
            o[j][0] *= a0; o[j][1] *= a0;
            o[j][2] *= a1; o[j][3] *= a1;
        }
        ol[0] *= a0; ol[1] *= a0;
        ol[2] *= a1; ol[3] *= a1;

        // O += P V (+ ones-column MMA accumulates row sums into ol)
#pragma unroll
        for (int ks2 = 0; ks2 < 8; ++ks2) {
            uint32_t pf[4] = {pp[2*ks2][0], pp[2*ks2][1], pp[2*ks2+1][0], pp[2*ks2+1][1]};
#pragma unroll
            for (int jp = 0; jp < 4; ++jp) {
                uint32_t voff = ((ks2 * 16 + vr) * FA_LD + jp * 16 + vc) * 2;
                uint32_t vh[4];
                LDM_X4T(vh, uVh + voff);
                MMA_F16R(o[2*jp],   pf, vh[0], vh[1]);
                MMA_F16R(o[2*jp+1], pf, vh[2], vh[3]);
            }
            uint32_t v1[2];
            uint32_t voff1 = ((ks2 * 16 + v1r) * FA_LD + 64) * 2;
            LDM_X2T(v1, uVh + voff1);
            MMA_F16R(ol, pf, v1[0], v1[1]);
        }

        if (kt < qt) { CP_WAIT0(); __syncthreads(); }
    }

    // epilogue: l lives in quad-leader's ol[0]/ol[2]; broadcast, normalize, store
    float l0 = __shfl_sync(0xffffffffu, ol[0], lane & ~3);
    float l1 = __shfl_sync(0xffffffffu, ol[2], lane & ~3);
    float inv0 = 1.f / l0;
    float inv1 = 1.f / l1;
    long grow0 = (long)b * S_ + q0 + wq * 16 + r0;
#pragma unroll
    for (int j = 0; j < 8; ++j) {
        int col = h * HD + j * 8 + c0;
        *(__half2*)&oh[grow0 * D_ + col] = __half2(
            __float2half_rn(o[j][0] * inv0), __float2half_rn(o[j][1] * inv0));
        *(__half2*)&oh[(grow0 + 8) * D_ + col] = __half2(
            __float2half_rn(o[j][2] * inv1), __float2half_rn(o[j][3] * inv1));
    }
}

// ---------------------------------------------------------------------------
extern "C" void kernel_launch(void* const* d_in, const int* in_sizes, int n_in,
                              void* d_out, int out_size)
{
    const float* x    = (const float*)d_in[0];
    const float* Wqkv = (const float*)d_in[1];
    const float* bqkv = (const float*)d_in[2];
    const float* Wp   = (const float*)d_in[3];
    const float* bp   = (const float*)d_in[4];
    float* out = (float*)d_out;

    __half *qh, *ah, *bhp;
    cudaGetSymbolAddress((void**)&qh, g_qh);
    cudaGetSymbolAddress((void**)&ah, g_ah);
    cudaGetSymbolAddress((void**)&bhp, g_bh);

    cudaFuncSetAttribute(gemm_mma_kernel<1>,
                         cudaFuncAttributeMaxDynamicSharedMemorySize, G_SMEM);
    cudaFuncSetAttribute(gemm_mma_kernel<0>,
                         cudaFuncAttributeMaxDynamicSharedMemorySize, G_SMEM);
    cudaFuncSetAttribute(flash_mma_kernel,
                         cudaFuncAttributeMaxDynamicSharedMemorySize, FA_SMEM);

    const int n4 = M_ * D_ / 4;
    const float qscale = 0.125f * 1.44269504088896340736f;   // 1/sqrt(hd) * log2(e)

    // 1) convert x -> fp16; convert Wqkv; QKV GEMM (1-term) -> fp16 (Q scaled)
    cvt_kernel<<<(n4 + 255) / 256, 256>>>(x, ah, n4);
    transpose_cvt_kernel<<<dim3(QKV_N / 32, D_ / 32), dim3(32, 8)>>>(Wqkv, bhp, D_, QKV_N);
    gemm_mma_kernel<1><<<dim3(QKV_N / 128, M_ / 128), 256, G_SMEM>>>(
        ah, bhp, bqkv, nullptr, qh, M_, QKV_N, D_, D_, qscale);

    // 2) flash attention (fp16 in/out, all 1-term)
    flash_mma_kernel<<<dim3(S_ / 128, B_ * H_), 256, FA_SMEM>>>(qh, ah);

    // 3) convert Wp; proj GEMM (1-term) -> fp32 out
    transpose_cvt_kernel<<<dim3(D_ / 32, D_ / 32), dim3(32, 8)>>>(Wp, bhp, D_, D_);
    gemm_mma_kernel<0><<<dim3(D_ / 128, M_ / 128), 256, G_SMEM>>>(
        ah, bhp, bp, out, nullptr, M_, D_, D_, 0, 1.f);
}